// round 1
// baseline (speedup 1.0000x reference)
#include <cuda_runtime.h>
#include <cuda_bf16.h>
#include <math.h>

#define BATCH 8
#define CT 16
#define LEN 2048
#define NDB 2048
#define NSEG 31
#define NPS 128
#define STEP 64
#define NF 65
#define TOPK 32
#define EPSV 1e-12f
#define PI_D 3.14159265358979323846264338327950288

// ---------------- scratch (__device__ globals; no allocation allowed) ------
__device__ float g_tab[NPS][NF][2];          // [t][f][{w*cos, -w*sin}]
__device__ float g_X[BATCH * CT * NSEG * NF * 2];   // target spectra (float2)
__device__ float g_Pxx[BATCH * CT * NF];
__device__ float g_scores[BATCH * CT * NDB];

// ---------------- kernel 0: twiddle table (Hann folded in, double prec) ----
__global__ void k_table() {
    int i = blockIdx.x * blockDim.x + threadIdx.x;
    if (i >= NPS * NF) return;
    int t = i / NF, f = i % NF;
    double w = 0.5 - 0.5 * cos(2.0 * PI_D * (double)t / (double)NPS);
    double ang = 2.0 * PI_D * (double)f * (double)t / (double)NPS;
    g_tab[t][f][0] = (float)(w * cos(ang));
    g_tab[t][f][1] = (float)(-w * sin(ang));
}

// ---------------- kernel 1: X spectra + Pxx (one block per (b,c)) ----------
__global__ __launch_bounds__(256) void k_xspec(const float* __restrict__ tgt) {
    int bc = blockIdx.x;               // b*CT + c
    int tid = threadIdx.x;
    __shared__ float sx[LEN];
    __shared__ float sfr[NSEG * NPS];
    __shared__ float smu[NSEG];
    __shared__ float sY[NSEG * NF * 2];

    const float* src = tgt + (size_t)bc * LEN;
    for (int i = tid; i < LEN; i += 256) sx[i] = src[i];
    __syncthreads();
    for (int s = tid; s < NSEG; s += 256) {
        float acc = 0.f;
        for (int t = 0; t < NPS; t++) acc += sx[s * STEP + t];
        smu[s] = acc * (1.f / NPS);
    }
    __syncthreads();
    for (int i = tid; i < NSEG * NPS; i += 256) {
        int s = i / NPS, t = i % NPS;
        sfr[i] = sx[s * STEP + t] - smu[s];
    }
    __syncthreads();
    for (int o = tid; o < NSEG * NF; o += 256) {
        int s = o / NF, f = o % NF;
        const float* fr = &sfr[s * NPS];
        float ar = 0.f, ai = 0.f;
        for (int t = 0; t < NPS; t++) {
            float v = fr[t];
            float2 tb = *(const float2*)&g_tab[t][f][0];
            ar = fmaf(v, tb.x, ar);
            ai = fmaf(v, tb.y, ai);
        }
        sY[o * 2] = ar; sY[o * 2 + 1] = ai;
        ((float2*)g_X)[(size_t)bc * (NSEG * NF) + o] = make_float2(ar, ai);
    }
    __syncthreads();
    if (tid < NF) {
        float acc = 0.f;
        for (int s = 0; s < NSEG; s++) {
            float ar = sY[(s * NF + tid) * 2];
            float ai = sY[(s * NF + tid) * 2 + 1];
            acc = fmaf(ar, ar, fmaf(ai, ai, acc));
        }
        g_Pxx[bc * NF + tid] = acc * (1.f / NSEG);
    }
}

// ---------------- kernel 2: scores (one block per (b,n)) -------------------
__global__ __launch_bounds__(256) void k_scores(const float* __restrict__ db) {
    int bn = blockIdx.x;
    int b = bn / NDB, n = bn % NDB;
    int tid = threadIdx.x;
    __shared__ float sx[LEN];
    __shared__ float sfr[NSEG * NPS];
    __shared__ float smu[NSEG];
    __shared__ float sY[NSEG * NF * 2];
    __shared__ float spyy[NF];
    __shared__ float scoh[NF];

    const float* src = db + (size_t)bn * LEN;
    for (int i = tid; i < LEN; i += 256) sx[i] = src[i];
    __syncthreads();
    for (int s = tid; s < NSEG; s += 256) {
        float acc = 0.f;
        for (int t = 0; t < NPS; t++) acc += sx[s * STEP + t];
        smu[s] = acc * (1.f / NPS);
    }
    __syncthreads();
    for (int i = tid; i < NSEG * NPS; i += 256) {
        int s = i / NPS, t = i % NPS;
        sfr[i] = sx[s * STEP + t] - smu[s];
    }
    __syncthreads();
    // direct DFT: Y[s][f]
    for (int o = tid; o < NSEG * NF; o += 256) {
        int s = o / NF, f = o % NF;
        const float* fr = &sfr[s * NPS];
        float ar = 0.f, ai = 0.f;
        for (int t = 0; t < NPS; t++) {
            float v = fr[t];
            float2 tb = *(const float2*)&g_tab[t][f][0];
            ar = fmaf(v, tb.x, ar);
            ai = fmaf(v, tb.y, ai);
        }
        sY[o * 2] = ar; sY[o * 2 + 1] = ai;
    }
    __syncthreads();
    // Pyy (deterministic, fixed order over s)
    if (tid < NF) {
        float acc = 0.f;
        for (int s = 0; s < NSEG; s++) {
            float ar = sY[(s * NF + tid) * 2];
            float ai = sY[(s * NF + tid) * 2 + 1];
            acc = fmaf(ar, ar, fmaf(ai, ai, acc));
        }
        spyy[tid] = acc * (1.f / NSEG);
    }
    __syncthreads();
    // coherence score against each of the CT target channels
    for (int c = 0; c < CT; c++) {
        if (tid < NF) {
            const float2* Xp = (const float2*)g_X
                + ((size_t)(b * CT + c)) * (NSEG * NF) + tid;
            float pr = 0.f, pi = 0.f;
            for (int s = 0; s < NSEG; s++) {
                float2 xv = Xp[(size_t)s * NF];
                float yr = sY[(s * NF + tid) * 2];
                float yi = sY[(s * NF + tid) * 2 + 1];
                // X * conj(Y)
                pr = fmaf(xv.x, yr, fmaf(xv.y, yi, pr));
                pi = fmaf(xv.y, yr, fmaf(-xv.x, yi, pi));
            }
            pr *= (1.f / NSEG); pi *= (1.f / NSEG);
            float pxx = g_Pxx[(b * CT + c) * NF + tid];
            scoh[tid] = fmaf(pr, pr, pi * pi) / (fmaf(pxx, spyy[tid], EPSV));
        }
        __syncthreads();
        if (tid == 0) {
            float acc = 0.f;
            for (int f = 0; f < NF; f++) acc += scoh[f];
            g_scores[(size_t)(b * CT + c) * NDB + n] = acc * (1.f / NF);
        }
        __syncthreads();
    }
}

// ---------------- kernel 3: top-32 + gather (one block per (b,c)) ----------
__global__ __launch_bounds__(256) void k_topk(const float* __restrict__ db,
                                              float* __restrict__ out) {
    int bc = blockIdx.x;
    int b = bc / CT;
    int tid = threadIdx.x;
    __shared__ float ss[NDB];
    __shared__ float rv[256];
    __shared__ int ri[256];
    __shared__ int sidx[TOPK];

    for (int i = tid; i < NDB; i += 256) ss[i] = g_scores[(size_t)bc * NDB + i];
    __syncthreads();

    for (int k = 0; k < TOPK; k++) {
        float bv = -3.402823466e+38f;
        int bi = NDB;
        for (int i = tid; i < NDB; i += 256) {
            float v = ss[i];
            if (v > bv) { bv = v; bi = i; }   // ascending scan keeps lowest idx on ties
        }
        rv[tid] = bv; ri[tid] = bi;
        __syncthreads();
        for (int ofs = 128; ofs > 0; ofs >>= 1) {
            if (tid < ofs) {
                float ov = rv[tid + ofs]; int oi = ri[tid + ofs];
                if (ov > rv[tid] || (ov == rv[tid] && oi < ri[tid])) {
                    rv[tid] = ov; ri[tid] = oi;
                }
            }
            __syncthreads();
        }
        if (tid == 0) { sidx[k] = ri[0]; ss[ri[0]] = -3.402823466e+38f; }
        __syncthreads();
    }

    // gather selected rows (vectorized float4)
    for (int k = 0; k < TOPK; k++) {
        int row = sidx[k];
        const float4* src = (const float4*)(db + ((size_t)b * NDB + row) * LEN);
        float4* dst = (float4*)(out + ((size_t)bc * TOPK + k) * LEN);
        for (int i = tid; i < LEN / 4; i += 256) dst[i] = src[i];
    }
}

// ---------------- launch ----------------------------------------------------
extern "C" void kernel_launch(void* const* d_in, const int* in_sizes, int n_in,
                              void* d_out, int out_size) {
    // identify inputs by size (target: 262144, db: 33554432)
    const float* tgt = (const float*)d_in[0];
    const float* db  = (const float*)d_in[1];
    if (n_in >= 2 && in_sizes[0] > in_sizes[1]) {
        tgt = (const float*)d_in[1];
        db  = (const float*)d_in[0];
    }
    float* out = (float*)d_out;

    k_table<<<(NPS * NF + 255) / 256, 256>>>();
    k_xspec<<<BATCH * CT, 256>>>(tgt);
    k_scores<<<BATCH * NDB, 256>>>(db);
    k_topk<<<BATCH * CT, 256>>>(db, out);
}

// round 3
// speedup vs baseline: 1.3582x; 1.3582x over previous
#include <cuda_runtime.h>
#include <cuda_bf16.h>
#include <math.h>

#define BATCH 8
#define CT 16
#define LEN 2048
#define NDB 2048
#define NSEG 31
#define NPS 128
#define STEP 64
#define NF 65
#define TOPK 32
#define EPSV 1e-12f
#define PI_D 3.14159265358979323846264338327950288

// ---------------- scratch (__device__ globals; no allocation allowed) ------
__device__ float2 g_tab[NPS * NF];                 // [t*NF+f] = {w*cos, -w*sin}
__device__ float2 g_X[BATCH * CT * NSEG * NF];     // target spectra
__device__ float  g_Pxx[BATCH * CT * NF];
__device__ float  g_scores[BATCH * CT * NDB];
__device__ int    g_sidx[BATCH * CT * TOPK];

// ---------------- kernel 0: twiddle table (Hann folded in, double prec) ----
__global__ void k_table() {
    int i = blockIdx.x * blockDim.x + threadIdx.x;
    if (i < NPS * NF) {
        int t = i / NF, f = i % NF;
        double w = 0.5 - 0.5 * cos(2.0 * PI_D * (double)t / (double)NPS);
        double ang = 2.0 * PI_D * (double)f * (double)t / (double)NPS;
        g_tab[t * NF + f] = make_float2((float)(w * cos(ang)), (float)(-w * sin(ang)));
    }
}

// ---------------- kernel 1: X spectra + Pxx (one block per (b,c)) ----------
// NOTE: numeric order here must stay identical to R0 (it matched bit-exactly).
__global__ __launch_bounds__(256) void k_xspec(const float* __restrict__ tgt) {
    int bc = blockIdx.x;               // b*CT + c
    int tid = threadIdx.x;
    __shared__ float sx[LEN];
    __shared__ float sfr[NSEG * NPS];
    __shared__ float smu[NSEG];
    __shared__ float sY[NSEG * NF * 2];

    const float* src = tgt + (size_t)bc * LEN;
    for (int i = tid; i < LEN; i += 256) sx[i] = src[i];
    __syncthreads();
    for (int s = tid; s < NSEG; s += 256) {
        float acc = 0.f;
        for (int t = 0; t < NPS; t++) acc += sx[s * STEP + t];
        smu[s] = acc * (1.f / NPS);
    }
    __syncthreads();
    for (int i = tid; i < NSEG * NPS; i += 256) {
        int s = i / NPS, t = i % NPS;
        sfr[i] = sx[s * STEP + t] - smu[s];
    }
    __syncthreads();
    for (int o = tid; o < NSEG * NF; o += 256) {
        int s = o / NF, f = o % NF;
        const float* fr = &sfr[s * NPS];
        float ar = 0.f, ai = 0.f;
        for (int t = 0; t < NPS; t++) {
            float v = fr[t];
            float2 tb = g_tab[t * NF + f];
            ar = fmaf(v, tb.x, ar);
            ai = fmaf(v, tb.y, ai);
        }
        sY[o * 2] = ar; sY[o * 2 + 1] = ai;
        g_X[(size_t)bc * (NSEG * NF) + o] = make_float2(ar, ai);
    }
    __syncthreads();
    if (tid < NF) {
        float acc = 0.f;
        for (int s = 0; s < NSEG; s++) {
            float ar = sY[(s * NF + tid) * 2];
            float ai = sY[(s * NF + tid) * 2 + 1];
            acc = fmaf(ar, ar, fmaf(ai, ai, acc));
        }
        g_Pxx[bc * NF + tid] = acc * (1.f / NSEG);
    }
}

// ---------------- kernel 2: scores (one block per (b,n)) -------------------
// Register-tiled direct DFT: thread handles 2 segments x 5 frequencies.
// Detrend done INLINE per sample (v = x[t] - mu): identical fp32 op order to
// the known-bit-exact R0 path (subtract, then fmaf with w-folded twiddle, t
// ascending). No post-correction.
__global__ __launch_bounds__(256) void k_scores(const float* __restrict__ db) {
    int bn = blockIdx.x;
    int b = bn / NDB;
    int tid = threadIdx.x;

    __shared__ float  sx[2112];            // padded (31*64+128), tail zeroed
    __shared__ float  smu[32];
    __shared__ float2 sY[NSEG * NF];       // 16120 B
    __shared__ float  spyy[NF];
    __shared__ float  scoh[CT * NF];       // 4160 B

    const float4* src = (const float4*)(db + (size_t)bn * LEN);
    for (int i = tid; i < LEN / 4; i += 256) ((float4*)sx)[i] = src[i];
    for (int i = LEN + tid; i < 2112; i += 256) sx[i] = 0.f;
    __syncthreads();

    if (tid < 32) {
        float acc = 0.f;
        if (tid < NSEG) {
            const float* p = &sx[tid * STEP];
            for (int t = 0; t < NPS; t++) acc += p[t];
        }
        smu[tid] = acc * (1.f / NPS);
    }
    __syncthreads();

    // ---- DFT: 16 s-chunks (T_S=2) x 13 f-chunks (T_F=5) = 208 work items ----
    if (tid < 208) {
        int sc = tid / 13, fc = tid % 13;
        int s0 = sc * 2, f0 = fc * 5;
        const float* fr0 = &sx[s0 * STEP];
        const float* fr1 = &sx[(s0 + 1) * STEP];
        float mu0 = smu[s0], mu1 = smu[s0 + 1];
        float ar0[5] = {0.f, 0.f, 0.f, 0.f, 0.f};
        float ai0[5] = {0.f, 0.f, 0.f, 0.f, 0.f};
        float ar1[5] = {0.f, 0.f, 0.f, 0.f, 0.f};
        float ai1[5] = {0.f, 0.f, 0.f, 0.f, 0.f};
        const float2* tabp = &g_tab[f0];
        #pragma unroll 4
        for (int t = 0; t < NPS; t++) {
            float v0 = fr0[t] - mu0;     // identical op to R0's sfr store
            float v1 = fr1[t] - mu1;
            #pragma unroll
            for (int j = 0; j < 5; j++) {
                float2 tb = __ldg(&tabp[t * NF + j]);
                ar0[j] = fmaf(v0, tb.x, ar0[j]);
                ai0[j] = fmaf(v0, tb.y, ai0[j]);
                ar1[j] = fmaf(v1, tb.x, ar1[j]);
                ai1[j] = fmaf(v1, tb.y, ai1[j]);
            }
        }
        #pragma unroll
        for (int j = 0; j < 5; j++) {
            sY[s0 * NF + f0 + j] = make_float2(ar0[j], ai0[j]);
            if (sc != 15)
                sY[(s0 + 1) * NF + f0 + j] = make_float2(ar1[j], ai1[j]);
        }
    }
    __syncthreads();

    // ---- Pyy (fixed ascending s order) ----
    if (tid < NF) {
        float acc = 0.f;
        for (int s = 0; s < NSEG; s++) {
            float2 y = sY[s * NF + tid];
            acc = fmaf(y.x, y.x, fmaf(y.y, y.y, acc));
        }
        spyy[tid] = acc * (1.f / NSEG);
    }
    __syncthreads();

    // ---- Pxy + coherence, all 256 threads over 16x65 items ----
    for (int item = tid; item < CT * NF; item += 256) {
        int c = item / NF, f = item % NF;
        const float2* Xp = g_X + ((size_t)(b * CT + c)) * (NSEG * NF) + f;
        float pr = 0.f, pi = 0.f;
        #pragma unroll 1
        for (int s = 0; s < NSEG; s++) {
            float2 xv = __ldg(&Xp[s * NF]);
            float2 yv = sY[s * NF + f];
            pr = fmaf(xv.x, yv.x, fmaf(xv.y, yv.y, pr));
            pi = fmaf(xv.y, yv.x, fmaf(-xv.x, yv.y, pi));
        }
        pr *= (1.f / NSEG); pi *= (1.f / NSEG);
        float pxx = g_Pxx[(b * CT + c) * NF + f];
        scoh[item] = fmaf(pr, pr, pi * pi) / fmaf(pxx, spyy[f], EPSV);
    }
    __syncthreads();

    if (tid < CT) {
        float acc = 0.f;
        for (int f = 0; f < NF; f++) acc += scoh[tid * NF + f];
        g_scores[(size_t)(b * CT + tid) * NDB + (bn % NDB)] = acc * (1.f / NF);
    }
}

// ---------------- kernel 3a: top-32 selection (one block per (b,c)) --------
__global__ __launch_bounds__(256) void k_sel() {
    int bc = blockIdx.x;
    int tid = threadIdx.x;
    __shared__ float ss[NDB];
    __shared__ float rv[256];
    __shared__ int ri[256];

    for (int i = tid; i < NDB; i += 256) ss[i] = g_scores[(size_t)bc * NDB + i];
    __syncthreads();

    for (int k = 0; k < TOPK; k++) {
        float bv = -3.402823466e+38f;
        int bi = NDB;
        for (int i = tid; i < NDB; i += 256) {
            float v = ss[i];
            if (v > bv) { bv = v; bi = i; }   // ascending scan keeps lowest idx on ties
        }
        rv[tid] = bv; ri[tid] = bi;
        __syncthreads();
        for (int ofs = 128; ofs > 0; ofs >>= 1) {
            if (tid < ofs) {
                float ov = rv[tid + ofs]; int oi = ri[tid + ofs];
                if (ov > rv[tid] || (ov == rv[tid] && oi < ri[tid])) {
                    rv[tid] = ov; ri[tid] = oi;
                }
            }
            __syncthreads();
        }
        if (tid == 0) { g_sidx[bc * TOPK + k] = ri[0]; ss[ri[0]] = -3.402823466e+38f; }
        __syncthreads();
    }
}

// ---------------- kernel 3b: gather (one block per (b,c,k)) ----------------
__global__ __launch_bounds__(256) void k_gather(const float* __restrict__ db,
                                                float* __restrict__ out) {
    int g = blockIdx.x;                  // bc*TOPK + k
    int bc = g / TOPK;
    int b = bc / CT;
    int row = g_sidx[g];
    const float4* src = (const float4*)(db + ((size_t)b * NDB + row) * LEN);
    float4* dst = (float4*)(out + (size_t)g * LEN);
    int tid = threadIdx.x;
    dst[tid] = src[tid];
    dst[tid + 256] = src[tid + 256];
}

// ---------------- launch ----------------------------------------------------
extern "C" void kernel_launch(void* const* d_in, const int* in_sizes, int n_in,
                              void* d_out, int out_size) {
    const float* tgt = (const float*)d_in[0];
    const float* db  = (const float*)d_in[1];
    if (n_in >= 2 && in_sizes[0] > in_sizes[1]) {
        tgt = (const float*)d_in[1];
        db  = (const float*)d_in[0];
    }
    float* out = (float*)d_out;

    k_table<<<(NPS * NF + 255) / 256, 256>>>();
    k_xspec<<<BATCH * CT, 256>>>(tgt);
    k_scores<<<BATCH * NDB, 256>>>(db);
    k_sel<<<BATCH * CT, 256>>>();
    k_gather<<<BATCH * CT * TOPK, 256>>>(db, out);
}

// round 4
// speedup vs baseline: 1.4461x; 1.0648x over previous
#include <cuda_runtime.h>
#include <cuda_bf16.h>
#include <math.h>

#define BATCH 8
#define CT 16
#define LEN 2048
#define NDB 2048
#define NSEG 31
#define NPS 128
#define STEP 64
#define NF 65
#define TOPK 32
#define EPSV 1e-12f
#define PI_D 3.14159265358979323846264338327950288

// ---------------- scratch (__device__ globals; no allocation allowed) ------
__device__ float2 g_tab[NF * NF];                  // [t*NF+f], t=0..64: {w*cos, -w*sin}
__device__ float2 g_X[BATCH * CT * NSEG * NF];     // target spectra
__device__ float  g_Pxx[BATCH * CT * NF];
__device__ float  g_scores[BATCH * CT * NDB];
__device__ int    g_sidx[BATCH * CT * TOPK];

// ---------------- kernel 0: half twiddle table (Hann folded, double prec) --
__global__ void k_table() {
    int i = blockIdx.x * blockDim.x + threadIdx.x;
    if (i < NF * NF) {
        int t = i / NF, f = i % NF;
        double w = 0.5 - 0.5 * cos(2.0 * PI_D * (double)t / (double)NPS);
        double ang = 2.0 * PI_D * (double)f * (double)t / (double)NPS;
        float ws = (t == 0 || t == 64) ? 0.f : (float)(-w * sin(ang));
        g_tab[i] = make_float2((float)(w * cos(ang)), ws);
    }
}

// ---------------- kernel 1: X spectra + Pxx (one block per (b,c)) ----------
// Tiny (128 blocks); numerics here only feed X / Pxx which both sides share.
__global__ __launch_bounds__(256) void k_xspec(const float* __restrict__ tgt) {
    int bc = blockIdx.x;
    int tid = threadIdx.x;
    __shared__ float sx[2176];
    __shared__ float smu[32];
    __shared__ float2 sY[NSEG * NF];

    const float* src = tgt + (size_t)bc * LEN;
    for (int i = tid; i < LEN; i += 256) sx[i] = src[i];
    for (int i = LEN + tid; i < 2176; i += 256) sx[i] = 0.f;
    __syncthreads();
    if (tid < 32) {
        float acc = 0.f;
        if (tid < NSEG) {
            const float* p = &sx[tid * STEP];
            for (int t = 0; t < NPS; t++) acc += p[t];
        }
        smu[tid] = acc * (1.f / NPS);
    }
    __syncthreads();
    for (int o = tid; o < NSEG * NF; o += 256) {
        int s = o / NF, f = o % NF;
        const float* fr = &sx[s * STEP];
        float mu = smu[s];
        float ar = 0.f, ai = 0.f;
        // symmetric form (matches k_scores' numeric order)
        {
            float v0 = fr[0] - mu;
            float2 tb = g_tab[f];            // t=0
            ar = fmaf(v0, tb.x, ar);
        }
        for (int t = 1; t < 64; t++) {
            float a = (fr[t] - mu) + (fr[128 - t] - mu);
            float d = fr[t] - fr[128 - t];
            float2 tb = g_tab[t * NF + f];
            ar = fmaf(a, tb.x, ar);
            ai = fmaf(d, tb.y, ai);
        }
        {
            float v64 = fr[64] - mu;
            float2 tb = g_tab[64 * NF + f];
            ar = fmaf(v64, tb.x, ar);
        }
        sY[o] = make_float2(ar, ai);
        g_X[(size_t)bc * (NSEG * NF) + o] = make_float2(ar, ai);
    }
    __syncthreads();
    if (tid < NF) {
        float acc = 0.f;
        for (int s = 0; s < NSEG; s++) {
            float2 y = sY[s * NF + tid];
            acc = fmaf(y.x, y.x, fmaf(y.y, y.y, acc));
        }
        g_Pxx[bc * NF + tid] = acc * (1.f / NSEG);
    }
}

// ---------------- kernel 2: scores (one block per (b,n)) -------------------
// Half-spectrum symmetric DFT: per segment fold A[t]=v[t]+v[128-t],
// D[t]=v[t]-v[128-t]; then 65-step dot per frequency (2x fewer FMAs/loads).
__global__ __launch_bounds__(256) void k_scores(const float* __restrict__ db) {
    int bn = blockIdx.x;
    int b = bn / NDB;
    int tid = threadIdx.x;

    __shared__ float  sx[2176];            // row + zero pad; reused as scoh later
    __shared__ float  smu[32];
    __shared__ float  sAD[NSEG * 128 + 192];  // [s][0..64]=A, [s][65..127]=D(t=1..63)
    __shared__ float2 sY[NSEG * NF];
    __shared__ float  spyy[NF];
    float* scoh = sx;                      // overlay: sx dead after sAD built

    const float4* src = (const float4*)(db + (size_t)bn * LEN);
    for (int i = tid; i < LEN / 4; i += 256) ((float4*)sx)[i] = src[i];
    for (int i = LEN + tid; i < 2176; i += 256) sx[i] = 0.f;
    __syncthreads();

    if (tid < 32) {
        float acc = 0.f;
        if (tid < NSEG) {
            const float* p = &sx[tid * STEP];
            for (int t = 0; t < NPS; t++) acc += p[t];
        }
        smu[tid] = acc * (1.f / NPS);
    }
    __syncthreads();

    // ---- fold: A/D arrays ----
    for (int i = tid; i < NSEG * 64; i += 256) {
        int s = i >> 6, t = i & 63;
        float mu = smu[s];
        const float* fr = &sx[s * STEP];
        if (t == 0) {
            sAD[s * 128] = fr[0] - mu;            // A[0]
            sAD[s * 128 + 64] = fr[64] - mu;      // A[64]
        } else {
            float x1 = fr[t], x2 = fr[128 - t];
            sAD[s * 128 + t] = (x1 - mu) + (x2 - mu);   // A[t]
            sAD[s * 128 + 64 + t] = x1 - x2;            // D[t]
        }
    }
    // zero pad beyond last segment (read by t=64 D-slot / sc=15 lane)
    for (int i = NSEG * 128 + tid; i < NSEG * 128 + 192; i += 256) sAD[i] = 0.f;
    __syncthreads();

    // ---- DFT: 16 s-chunks (2 segs) x 13 f-chunks (5 freqs), t = 0..64 ----
    if (tid < 208) {
        int sc = tid / 13, fc = tid % 13;
        int s0 = sc * 2, f0 = fc * 5;
        const float* p0 = &sAD[s0 * 128];
        const float* p1 = &sAD[s0 * 128 + 128];
        float ar0[5] = {0,0,0,0,0}, ai0[5] = {0,0,0,0,0};
        float ar1[5] = {0,0,0,0,0}, ai1[5] = {0,0,0,0,0};
        const float2* tabp = &g_tab[f0];
        #pragma unroll 5
        for (int t = 0; t <= 64; t++) {
            float A0 = p0[t], D0 = p0[64 + t];   // D slot at t=0/64 is finite junk x 0
            float A1 = p1[t], D1 = p1[64 + t];
            #pragma unroll
            for (int j = 0; j < 5; j++) {
                float2 tb = __ldg(&tabp[t * NF + j]);
                ar0[j] = fmaf(A0, tb.x, ar0[j]);
                ai0[j] = fmaf(D0, tb.y, ai0[j]);
                ar1[j] = fmaf(A1, tb.x, ar1[j]);
                ai1[j] = fmaf(D1, tb.y, ai1[j]);
            }
        }
        #pragma unroll
        for (int j = 0; j < 5; j++) {
            sY[s0 * NF + f0 + j] = make_float2(ar0[j], ai0[j]);
            if (sc != 15)
                sY[(s0 + 1) * NF + f0 + j] = make_float2(ar1[j], ai1[j]);
        }
    }
    __syncthreads();

    // ---- Pyy ----
    if (tid < NF) {
        float acc = 0.f;
        for (int s = 0; s < NSEG; s++) {
            float2 y = sY[s * NF + tid];
            acc = fmaf(y.x, y.x, fmaf(y.y, y.y, acc));
        }
        spyy[tid] = acc * (1.f / NSEG);
    }
    __syncthreads();

    // ---- Pxy + coherence over 16x65 items ----
    for (int item = tid; item < CT * NF; item += 256) {
        int c = item / NF, f = item % NF;
        const float2* Xp = g_X + ((size_t)(b * CT + c)) * (NSEG * NF) + f;
        float pr = 0.f, pi = 0.f;
        #pragma unroll 1
        for (int s = 0; s < NSEG; s++) {
            float2 xv = __ldg(&Xp[s * NF]);
            float2 yv = sY[s * NF + f];
            pr = fmaf(xv.x, yv.x, fmaf(xv.y, yv.y, pr));
            pi = fmaf(xv.y, yv.x, fmaf(-xv.x, yv.y, pi));
        }
        pr *= (1.f / NSEG); pi *= (1.f / NSEG);
        float pxx = g_Pxx[(b * CT + c) * NF + f];
        scoh[item] = fmaf(pr, pr, pi * pi) / fmaf(pxx, spyy[f], EPSV);
    }
    __syncthreads();

    if (tid < CT) {
        float acc = 0.f;
        for (int f = 0; f < NF; f++) acc += scoh[tid * NF + f];
        g_scores[(size_t)(b * CT + tid) * NDB + (bn % NDB)] = acc * (1.f / NF);
    }
}

// ---------------- kernel 3a: top-32 selection (one block per (b,c)) --------
__global__ __launch_bounds__(256) void k_sel() {
    int bc = blockIdx.x;
    int tid = threadIdx.x;
    __shared__ float ss[NDB];
    __shared__ float rv[256];
    __shared__ int ri[256];

    for (int i = tid; i < NDB; i += 256) ss[i] = g_scores[(size_t)bc * NDB + i];
    __syncthreads();

    for (int k = 0; k < TOPK; k++) {
        float bv = -3.402823466e+38f;
        int bi = NDB;
        for (int i = tid; i < NDB; i += 256) {
            float v = ss[i];
            if (v > bv) { bv = v; bi = i; }
        }
        rv[tid] = bv; ri[tid] = bi;
        __syncthreads();
        for (int ofs = 128; ofs > 0; ofs >>= 1) {
            if (tid < ofs) {
                float ov = rv[tid + ofs]; int oi = ri[tid + ofs];
                if (ov > rv[tid] || (ov == rv[tid] && oi < ri[tid])) {
                    rv[tid] = ov; ri[tid] = oi;
                }
            }
            __syncthreads();
        }
        if (tid == 0) { g_sidx[bc * TOPK + k] = ri[0]; ss[ri[0]] = -3.402823466e+38f; }
        __syncthreads();
    }
}

// ---------------- kernel 3b: gather (one block per (b,c,k)) ----------------
__global__ __launch_bounds__(256) void k_gather(const float* __restrict__ db,
                                                float* __restrict__ out) {
    int g = blockIdx.x;
    int bc = g / TOPK;
    int b = bc / CT;
    int row = g_sidx[g];
    const float4* src = (const float4*)(db + ((size_t)b * NDB + row) * LEN);
    float4* dst = (float4*)(out + (size_t)g * LEN);
    int tid = threadIdx.x;
    dst[tid] = src[tid];
    dst[tid + 256] = src[tid + 256];
}

// ---------------- launch ----------------------------------------------------
extern "C" void kernel_launch(void* const* d_in, const int* in_sizes, int n_in,
                              void* d_out, int out_size) {
    const float* tgt = (const float*)d_in[0];
    const float* db  = (const float*)d_in[1];
    if (n_in >= 2 && in_sizes[0] > in_sizes[1]) {
        tgt = (const float*)d_in[1];
        db  = (const float*)d_in[0];
    }
    float* out = (float*)d_out;

    k_table<<<(NF * NF + 255) / 256, 256>>>();
    k_xspec<<<BATCH * CT, 256>>>(tgt);
    k_scores<<<BATCH * NDB, 256>>>(db);
    k_sel<<<BATCH * CT, 256>>>();
    k_gather<<<BATCH * CT * TOPK, 256>>>(db, out);
}

// round 5
// speedup vs baseline: 1.7058x; 1.1796x over previous
#include <cuda_runtime.h>
#include <cuda_bf16.h>
#include <math.h>

#define BATCH 8
#define CT 16
#define LEN 2048
#define NDB 2048
#define NSEG 31
#define NPS 128
#define STEP 64
#define NF 65
#define TABW 66            // padded table stride (16B-aligned float2 rows)
#define TOPK 32
#define EPSV 1e-12f
#define PI_D 3.14159265358979323846264338327950288

// ---------------- scratch (__device__ globals; no allocation allowed) ------
__device__ float2 g_tab[NF * TABW];                // [t*TABW+f], t=0..64: {w*cos, -w*sin}
__device__ float2 g_X[BATCH * CT * NSEG * NF];     // target spectra
__device__ float  g_Pxx[BATCH * CT * NF];
__device__ float  g_scores[BATCH * CT * NDB];
__device__ int    g_sidx[BATCH * CT * TOPK];

// ---------------- kernel 0: half twiddle table (Hann folded, double prec) --
__global__ void k_table() {
    int i = blockIdx.x * blockDim.x + threadIdx.x;
    if (i < NF * TABW) {
        int t = i / TABW, f = i % TABW;
        if (f < NF) {
            double w = 0.5 - 0.5 * cos(2.0 * PI_D * (double)t / (double)NPS);
            double ang = 2.0 * PI_D * (double)f * (double)t / (double)NPS;
            float ws = (t == 0 || t == 64) ? 0.f : (float)(-w * sin(ang));
            g_tab[i] = make_float2((float)(w * cos(ang)), ws);
        } else {
            g_tab[i] = make_float2(0.f, 0.f);
        }
    }
}

// ---------------- kernel 1: X spectra + Pxx (one block per (b,c)) ----------
__global__ __launch_bounds__(256) void k_xspec(const float* __restrict__ tgt) {
    int bc = blockIdx.x;
    int tid = threadIdx.x;
    __shared__ float sx[2176];
    __shared__ float smu[32];
    __shared__ float2 sY[NSEG * NF];

    const float* src = tgt + (size_t)bc * LEN;
    for (int i = tid; i < LEN; i += 256) sx[i] = src[i];
    for (int i = LEN + tid; i < 2176; i += 256) sx[i] = 0.f;
    __syncthreads();
    if (tid < 32) {
        float acc = 0.f;
        if (tid < NSEG) {
            const float* p = &sx[tid * STEP];
            for (int t = 0; t < NPS; t++) acc += p[t];
        }
        smu[tid] = acc * (1.f / NPS);
    }
    __syncthreads();
    for (int o = tid; o < NSEG * NF; o += 256) {
        int s = o / NF, f = o % NF;
        const float* fr = &sx[s * STEP];
        float mu = smu[s];
        float ar = 0.f, ai = 0.f;
        {
            float v0 = fr[0] - mu;
            float2 tb = g_tab[f];                 // t=0
            ar = fmaf(v0, tb.x, ar);
        }
        for (int t = 1; t < 64; t++) {
            float a = (fr[t] - mu) + (fr[128 - t] - mu);
            float d = fr[t] - fr[128 - t];
            float2 tb = g_tab[t * TABW + f];
            ar = fmaf(a, tb.x, ar);
            ai = fmaf(d, tb.y, ai);
        }
        {
            float v64 = fr[64] - mu;
            float2 tb = g_tab[64 * TABW + f];
            ar = fmaf(v64, tb.x, ar);
        }
        sY[o] = make_float2(ar, ai);
        g_X[(size_t)bc * (NSEG * NF) + o] = make_float2(ar, ai);
    }
    __syncthreads();
    if (tid < NF) {
        float acc = 0.f;
        for (int s = 0; s < NSEG; s++) {
            float2 y = sY[s * NF + tid];
            acc = fmaf(y.x, y.x, fmaf(y.y, y.y, acc));
        }
        g_Pxx[bc * NF + tid] = acc * (1.f / NSEG);
    }
}

// ---------------- kernel 2: scores (one block per (b,n)) -------------------
// DFT remap: lane = segment, warp = 8-freq group. Uniform LDG.128 twiddle
// loads (1 wavefront/warp-load, L1-hot) + packed fma.rn.f32x2 per (f,t).
// Per-(s,f) accumulation order over t identical to R4 (bit-exact).
__global__ __launch_bounds__(256) void k_scores(const float* __restrict__ db) {
    int bn = blockIdx.x;
    int b = bn / NDB;
    int tid = threadIdx.x;

    __shared__ float  sx[2176];                // row + pad; reused as scoh
    __shared__ float  smu[32];
    __shared__ float  sAD[32 * 129];           // per-seg: A[0..64], D@65..127, 0@128
    __shared__ float2 sY[NSEG * NF];
    __shared__ float  spyy[NF];
    float* scoh = sx;

    const float4* src = (const float4*)(db + (size_t)bn * LEN);
    for (int i = tid; i < LEN / 4; i += 256) ((float4*)sx)[i] = src[i];
    for (int i = LEN + tid; i < 2176; i += 256) sx[i] = 0.f;
    __syncthreads();

    if (tid < 32) {
        float acc = 0.f;
        if (tid < NSEG) {
            const float* p = &sx[tid * STEP];
            for (int t = 0; t < NPS; t++) acc += p[t];
        }
        smu[tid] = acc * (1.f / NPS);
    }
    __syncthreads();

    // ---- fold: A/D arrays, stride 129 (bank-conflict-free for lane=s) ----
    for (int i = tid; i < NSEG * 64; i += 256) {
        int s = i >> 6, t = i & 63;
        float mu = smu[s];
        const float* fr = &sx[s * STEP];
        int base = s * 129;
        if (t == 0) {
            sAD[base]       = fr[0] - mu;          // A[0]
            sAD[base + 64]  = fr[64] - mu;         // A[64]
            sAD[base + 128] = 0.f;                 // D[64] pad
        } else {
            float x1 = fr[t], x2 = fr[128 - t];
            sAD[base + t]      = (x1 - mu) + (x2 - mu);  // A[t]
            sAD[base + 64 + t] = x1 - x2;                // D[t]
        }
    }
    for (int i = 31 * 129 + tid; i < 32 * 129; i += 256) sAD[i] = 0.f;  // idle lane
    __syncthreads();

    // ---- DFT: warp w -> freqs [8w, 8w+8) (+ f=64 on warp 0); lane = seg ----
    {
        int w = tid >> 5, lane = tid & 31;
        const float* p = &sAD[lane * 129];
        int f0 = w * 8;
        unsigned long long acc[8] = {0ull,0ull,0ull,0ull,0ull,0ull,0ull,0ull};
        unsigned long long acc64 = 0ull;
        #pragma unroll 1
        for (int t = 0; t <= 64; t++) {
            float A = p[t], D = p[64 + t];         // t=0: D slot = A[64], ws=0
            unsigned long long ad;
            asm("mov.b64 %0, {%1,%2};" : "=l"(ad)
                : "r"(__float_as_uint(A)), "r"(__float_as_uint(D)));
            const ulonglong2* tq =
                (const ulonglong2*)(g_tab + (size_t)t * TABW + f0);
            ulonglong2 q0 = __ldg(tq);
            ulonglong2 q1 = __ldg(tq + 1);
            ulonglong2 q2 = __ldg(tq + 2);
            ulonglong2 q3 = __ldg(tq + 3);
            asm("fma.rn.f32x2 %0, %1, %2, %0;" : "+l"(acc[0]) : "l"(ad), "l"(q0.x));
            asm("fma.rn.f32x2 %0, %1, %2, %0;" : "+l"(acc[1]) : "l"(ad), "l"(q0.y));
            asm("fma.rn.f32x2 %0, %1, %2, %0;" : "+l"(acc[2]) : "l"(ad), "l"(q1.x));
            asm("fma.rn.f32x2 %0, %1, %2, %0;" : "+l"(acc[3]) : "l"(ad), "l"(q1.y));
            asm("fma.rn.f32x2 %0, %1, %2, %0;" : "+l"(acc[4]) : "l"(ad), "l"(q2.x));
            asm("fma.rn.f32x2 %0, %1, %2, %0;" : "+l"(acc[5]) : "l"(ad), "l"(q2.y));
            asm("fma.rn.f32x2 %0, %1, %2, %0;" : "+l"(acc[6]) : "l"(ad), "l"(q3.x));
            asm("fma.rn.f32x2 %0, %1, %2, %0;" : "+l"(acc[7]) : "l"(ad), "l"(q3.y));
            if (w == 0) {
                unsigned long long t64 =
                    *(const unsigned long long*)(g_tab + (size_t)t * TABW + 64);
                asm("fma.rn.f32x2 %0, %1, %2, %0;" : "+l"(acc64) : "l"(ad), "l"(t64));
            }
        }
        if (lane < NSEG) {
            #pragma unroll
            for (int j = 0; j < 8; j++) {
                unsigned int lo, hi;
                asm("mov.b64 {%0,%1}, %2;" : "=r"(lo), "=r"(hi) : "l"(acc[j]));
                sY[lane * NF + f0 + j] =
                    make_float2(__uint_as_float(lo), __uint_as_float(hi));
            }
            if (w == 0) {
                unsigned int lo, hi;
                asm("mov.b64 {%0,%1}, %2;" : "=r"(lo), "=r"(hi) : "l"(acc64));
                sY[lane * NF + 64] =
                    make_float2(__uint_as_float(lo), __uint_as_float(hi));
            }
        }
    }
    __syncthreads();

    // ---- Pyy ----
    if (tid < NF) {
        float acc = 0.f;
        for (int s = 0; s < NSEG; s++) {
            float2 y = sY[s * NF + tid];
            acc = fmaf(y.x, y.x, fmaf(y.y, y.y, acc));
        }
        spyy[tid] = acc * (1.f / NSEG);
    }
    __syncthreads();

    // ---- Pxy + coherence over 16x65 items ----
    for (int item = tid; item < CT * NF; item += 256) {
        int c = item / NF, f = item % NF;
        const float2* Xp = g_X + ((size_t)(b * CT + c)) * (NSEG * NF) + f;
        float pr = 0.f, pi = 0.f;
        #pragma unroll 1
        for (int s = 0; s < NSEG; s++) {
            float2 xv = __ldg(&Xp[s * NF]);
            float2 yv = sY[s * NF + f];
            pr = fmaf(xv.x, yv.x, fmaf(xv.y, yv.y, pr));
            pi = fmaf(xv.y, yv.x, fmaf(-xv.x, yv.y, pi));
        }
        pr *= (1.f / NSEG); pi *= (1.f / NSEG);
        float pxx = g_Pxx[(b * CT + c) * NF + f];
        scoh[item] = fmaf(pr, pr, pi * pi) / fmaf(pxx, spyy[f], EPSV);
    }
    __syncthreads();

    if (tid < CT) {
        float acc = 0.f;
        for (int f = 0; f < NF; f++) acc += scoh[tid * NF + f];
        g_scores[(size_t)(b * CT + tid) * NDB + (bn % NDB)] = acc * (1.f / NF);
    }
}

// ---------------- kernel 3a: top-32 selection (one block per (b,c)) --------
__global__ __launch_bounds__(256) void k_sel() {
    int bc = blockIdx.x;
    int tid = threadIdx.x;
    __shared__ float ss[NDB];
    __shared__ float rv[256];
    __shared__ int ri[256];

    for (int i = tid; i < NDB; i += 256) ss[i] = g_scores[(size_t)bc * NDB + i];
    __syncthreads();

    for (int k = 0; k < TOPK; k++) {
        float bv = -3.402823466e+38f;
        int bi = NDB;
        for (int i = tid; i < NDB; i += 256) {
            float v = ss[i];
            if (v > bv) { bv = v; bi = i; }
        }
        rv[tid] = bv; ri[tid] = bi;
        __syncthreads();
        for (int ofs = 128; ofs > 0; ofs >>= 1) {
            if (tid < ofs) {
                float ov = rv[tid + ofs]; int oi = ri[tid + ofs];
                if (ov > rv[tid] || (ov == rv[tid] && oi < ri[tid])) {
                    rv[tid] = ov; ri[tid] = oi;
                }
            }
            __syncthreads();
        }
        if (tid == 0) { g_sidx[bc * TOPK + k] = ri[0]; ss[ri[0]] = -3.402823466e+38f; }
        __syncthreads();
    }
}

// ---------------- kernel 3b: gather (one block per (b,c,k)) ----------------
__global__ __launch_bounds__(256) void k_gather(const float* __restrict__ db,
                                                float* __restrict__ out) {
    int g = blockIdx.x;
    int bc = g / TOPK;
    int b = bc / CT;
    int row = g_sidx[g];
    const float4* src = (const float4*)(db + ((size_t)b * NDB + row) * LEN);
    float4* dst = (float4*)(out + (size_t)g * LEN);
    int tid = threadIdx.x;
    dst[tid] = src[tid];
    dst[tid + 256] = src[tid + 256];
}

// ---------------- launch ----------------------------------------------------
extern "C" void kernel_launch(void* const* d_in, const int* in_sizes, int n_in,
                              void* d_out, int out_size) {
    const float* tgt = (const float*)d_in[0];
    const float* db  = (const float*)d_in[1];
    if (n_in >= 2 && in_sizes[0] > in_sizes[1]) {
        tgt = (const float*)d_in[1];
        db  = (const float*)d_in[0];
    }
    float* out = (float*)d_out;

    k_table<<<(NF * TABW + 255) / 256, 256>>>();
    k_xspec<<<BATCH * CT, 256>>>(tgt);
    k_scores<<<BATCH * NDB, 256>>>(db);
    k_sel<<<BATCH * CT, 256>>>();
    k_gather<<<BATCH * CT * TOPK, 256>>>(db, out);
}

// round 6
// speedup vs baseline: 2.2029x; 1.2914x over previous
#include <cuda_runtime.h>
#include <cuda_bf16.h>
#include <math.h>

#define BATCH 8
#define CT 16
#define LEN 2048
#define NDB 2048
#define NSEG 31
#define NPS 128
#define STEP 64
#define NF 65
#define TABW 66            // padded table stride (16B-aligned float2 rows)
#define TOPK 32
#define EPSV 1e-12f
#define PI_D 3.14159265358979323846264338327950288

// ---------------- scratch (__device__ globals; no allocation allowed) ------
__device__ float2 g_tab[NF * TABW];                // [t*TABW+f], t=0..64: {w*cos, -w*sin}
__device__ float2 g_X[BATCH * CT * NSEG * NF];     // target spectra
__device__ float  g_Pxx[BATCH * CT * NF];
__device__ float  g_scores[BATCH * CT * NDB];
__device__ int    g_sidx[BATCH * CT * TOPK];

// ---------------- kernel 0: half twiddle table (Hann folded, double prec) --
__global__ void k_table() {
    int i = blockIdx.x * blockDim.x + threadIdx.x;
    if (i < NF * TABW) {
        int t = i / TABW, f = i % TABW;
        if (f < NF) {
            double w = 0.5 - 0.5 * cos(2.0 * PI_D * (double)t / (double)NPS);
            double ang = 2.0 * PI_D * (double)f * (double)t / (double)NPS;
            float ws = (t == 0 || t == 64) ? 0.f : (float)(-w * sin(ang));
            g_tab[i] = make_float2((float)(w * cos(ang)), ws);
        } else {
            g_tab[i] = make_float2(0.f, 0.f);
        }
    }
}

// ---------------- kernel 1: X spectra + Pxx (one block per (b,c)) ----------
__global__ __launch_bounds__(256) void k_xspec(const float* __restrict__ tgt) {
    int bc = blockIdx.x;
    int tid = threadIdx.x;
    __shared__ float sx[2176];
    __shared__ float smu[32];
    __shared__ float2 sY[NSEG * NF];

    const float* src = tgt + (size_t)bc * LEN;
    for (int i = tid; i < LEN; i += 256) sx[i] = src[i];
    for (int i = LEN + tid; i < 2176; i += 256) sx[i] = 0.f;
    __syncthreads();
    if (tid < 32) {
        float acc = 0.f;
        if (tid < NSEG) {
            const float* p = &sx[tid * STEP];
            for (int t = 0; t < NPS; t++) acc += p[t];
        }
        smu[tid] = acc * (1.f / NPS);
    }
    __syncthreads();
    for (int o = tid; o < NSEG * NF; o += 256) {
        int s = o / NF, f = o % NF;
        const float* fr = &sx[s * STEP];
        float mu = smu[s];
        float ar = 0.f, ai = 0.f;
        {
            float v0 = fr[0] - mu;
            float2 tb = g_tab[f];                 // t=0
            ar = fmaf(v0, tb.x, ar);
        }
        for (int t = 1; t < 64; t++) {
            float a = (fr[t] - mu) + (fr[128 - t] - mu);
            float d = fr[t] - fr[128 - t];
            float2 tb = g_tab[t * TABW + f];
            ar = fmaf(a, tb.x, ar);
            ai = fmaf(d, tb.y, ai);
        }
        {
            float v64 = fr[64] - mu;
            float2 tb = g_tab[64 * TABW + f];
            ar = fmaf(v64, tb.x, ar);
        }
        sY[o] = make_float2(ar, ai);
        g_X[(size_t)bc * (NSEG * NF) + o] = make_float2(ar, ai);
    }
    __syncthreads();
    if (tid < NF) {
        float acc = 0.f;
        for (int s = 0; s < NSEG; s++) {
            float2 y = sY[s * NF + tid];
            acc = fmaf(y.x, y.x, fmaf(y.y, y.y, acc));
        }
        g_Pxx[bc * NF + tid] = acc * (1.f / NSEG);
    }
}

// ---------------- kernel 2: scores (one block per (b,n)) -------------------
// lane=segment / warp=8-freq DFT with uniform LDG.128 twiddles + fma.rn.f32x2.
// R6: unrolled hot loops (DFT x2, Pxy x4) for MLP; accumulator order unchanged.
__global__ __launch_bounds__(256) void k_scores(const float* __restrict__ db) {
    int bn = blockIdx.x;
    int b = bn / NDB;
    int tid = threadIdx.x;

    __shared__ float  sx[2176];                // row + pad; reused as scoh
    __shared__ float  smu[32];
    __shared__ float  sAD[32 * 129];           // per-seg: A[0..64], D@65..127, 0@128
    __shared__ float2 sY[NSEG * NF];
    __shared__ float  spyy[NF];
    float* scoh = sx;

    const float4* src = (const float4*)(db + (size_t)bn * LEN);
    for (int i = tid; i < LEN / 4; i += 256) ((float4*)sx)[i] = src[i];
    for (int i = LEN + tid; i < 2176; i += 256) sx[i] = 0.f;
    __syncthreads();

    if (tid < 32) {
        float acc = 0.f;
        if (tid < NSEG) {
            const float* p = &sx[tid * STEP];
            for (int t = 0; t < NPS; t++) acc += p[t];
        }
        smu[tid] = acc * (1.f / NPS);
    }
    __syncthreads();

    // ---- fold: A/D arrays, stride 129 (bank-conflict-free for lane=s) ----
    for (int i = tid; i < NSEG * 64; i += 256) {
        int s = i >> 6, t = i & 63;
        float mu = smu[s];
        const float* fr = &sx[s * STEP];
        int base = s * 129;
        if (t == 0) {
            sAD[base]       = fr[0] - mu;          // A[0]
            sAD[base + 64]  = fr[64] - mu;         // A[64]
            sAD[base + 128] = 0.f;                 // D[64] pad
        } else {
            float x1 = fr[t], x2 = fr[128 - t];
            sAD[base + t]      = (x1 - mu) + (x2 - mu);  // A[t]
            sAD[base + 64 + t] = x1 - x2;                // D[t]
        }
    }
    for (int i = 31 * 129 + tid; i < 32 * 129; i += 256) sAD[i] = 0.f;  // idle lane
    __syncthreads();

    // ---- DFT: warp w -> freqs [8w, 8w+8) (+ f=64 on warp 0); lane = seg ----
    {
        int w = tid >> 5, lane = tid & 31;
        const float* p = &sAD[lane * 129];
        int f0 = w * 8;
        unsigned long long acc[8] = {0ull,0ull,0ull,0ull,0ull,0ull,0ull,0ull};
        unsigned long long acc64 = 0ull;
        #pragma unroll 5
        for (int t = 0; t <= 64; t++) {
            float A = p[t], D = p[64 + t];         // t=0: D slot = A[64], ws=0
            unsigned long long ad;
            asm("mov.b64 %0, {%1,%2};" : "=l"(ad)
                : "r"(__float_as_uint(A)), "r"(__float_as_uint(D)));
            const ulonglong2* tq =
                (const ulonglong2*)(g_tab + (size_t)t * TABW + f0);
            ulonglong2 q0 = __ldg(tq);
            ulonglong2 q1 = __ldg(tq + 1);
            ulonglong2 q2 = __ldg(tq + 2);
            ulonglong2 q3 = __ldg(tq + 3);
            asm("fma.rn.f32x2 %0, %1, %2, %0;" : "+l"(acc[0]) : "l"(ad), "l"(q0.x));
            asm("fma.rn.f32x2 %0, %1, %2, %0;" : "+l"(acc[1]) : "l"(ad), "l"(q0.y));
            asm("fma.rn.f32x2 %0, %1, %2, %0;" : "+l"(acc[2]) : "l"(ad), "l"(q1.x));
            asm("fma.rn.f32x2 %0, %1, %2, %0;" : "+l"(acc[3]) : "l"(ad), "l"(q1.y));
            asm("fma.rn.f32x2 %0, %1, %2, %0;" : "+l"(acc[4]) : "l"(ad), "l"(q2.x));
            asm("fma.rn.f32x2 %0, %1, %2, %0;" : "+l"(acc[5]) : "l"(ad), "l"(q2.y));
            asm("fma.rn.f32x2 %0, %1, %2, %0;" : "+l"(acc[6]) : "l"(ad), "l"(q3.x));
            asm("fma.rn.f32x2 %0, %1, %2, %0;" : "+l"(acc[7]) : "l"(ad), "l"(q3.y));
            if (w == 0) {
                unsigned long long t64 =
                    *(const unsigned long long*)(g_tab + (size_t)t * TABW + 64);
                asm("fma.rn.f32x2 %0, %1, %2, %0;" : "+l"(acc64) : "l"(ad), "l"(t64));
            }
        }
        if (lane < NSEG) {
            #pragma unroll
            for (int j = 0; j < 8; j++) {
                unsigned int lo, hi;
                asm("mov.b64 {%0,%1}, %2;" : "=r"(lo), "=r"(hi) : "l"(acc[j]));
                sY[lane * NF + f0 + j] =
                    make_float2(__uint_as_float(lo), __uint_as_float(hi));
            }
            if (w == 0) {
                unsigned int lo, hi;
                asm("mov.b64 {%0,%1}, %2;" : "=r"(lo), "=r"(hi) : "l"(acc64));
                sY[lane * NF + 64] =
                    make_float2(__uint_as_float(lo), __uint_as_float(hi));
            }
        }
    }
    __syncthreads();

    // ---- Pyy ----
    if (tid < NF) {
        float acc = 0.f;
        #pragma unroll 4
        for (int s = 0; s < NSEG; s++) {
            float2 y = sY[s * NF + tid];
            acc = fmaf(y.x, y.x, fmaf(y.y, y.y, acc));
        }
        spyy[tid] = acc * (1.f / NSEG);
    }
    __syncthreads();

    // ---- Pxy + coherence over 16x65 items (unroll 4 for L2-hit MLP) ----
    for (int item = tid; item < CT * NF; item += 256) {
        int c = item / NF, f = item % NF;
        const float2* Xp = g_X + ((size_t)(b * CT + c)) * (NSEG * NF) + f;
        float pr = 0.f, pi = 0.f;
        #pragma unroll 4
        for (int s = 0; s < NSEG; s++) {
            float2 xv = __ldg(&Xp[s * NF]);
            float2 yv = sY[s * NF + f];
            pr = fmaf(xv.x, yv.x, fmaf(xv.y, yv.y, pr));
            pi = fmaf(xv.y, yv.x, fmaf(-xv.x, yv.y, pi));
        }
        pr *= (1.f / NSEG); pi *= (1.f / NSEG);
        float pxx = g_Pxx[(b * CT + c) * NF + f];
        scoh[item] = fmaf(pr, pr, pi * pi) / fmaf(pxx, spyy[f], EPSV);
    }
    __syncthreads();

    if (tid < CT) {
        float acc = 0.f;
        for (int f = 0; f < NF; f++) acc += scoh[tid * NF + f];
        g_scores[(size_t)(b * CT + tid) * NDB + (bn % NDB)] = acc * (1.f / NF);
    }
}

// ---------------- kernel 3a: top-32 selection (one block per (b,c)) --------
__global__ __launch_bounds__(256) void k_sel() {
    int bc = blockIdx.x;
    int tid = threadIdx.x;
    __shared__ float ss[NDB];
    __shared__ float rv[256];
    __shared__ int ri[256];

    for (int i = tid; i < NDB; i += 256) ss[i] = g_scores[(size_t)bc * NDB + i];
    __syncthreads();

    for (int k = 0; k < TOPK; k++) {
        float bv = -3.402823466e+38f;
        int bi = NDB;
        for (int i = tid; i < NDB; i += 256) {
            float v = ss[i];
            if (v > bv) { bv = v; bi = i; }
        }
        rv[tid] = bv; ri[tid] = bi;
        __syncthreads();
        for (int ofs = 128; ofs > 0; ofs >>= 1) {
            if (tid < ofs) {
                float ov = rv[tid + ofs]; int oi = ri[tid + ofs];
                if (ov > rv[tid] || (ov == rv[tid] && oi < ri[tid])) {
                    rv[tid] = ov; ri[tid] = oi;
                }
            }
            __syncthreads();
        }
        if (tid == 0) { g_sidx[bc * TOPK + k] = ri[0]; ss[ri[0]] = -3.402823466e+38f; }
        __syncthreads();
    }
}

// ---------------- kernel 3b: gather (one block per (b,c,k)) ----------------
__global__ __launch_bounds__(256) void k_gather(const float* __restrict__ db,
                                                float* __restrict__ out) {
    int g = blockIdx.x;
    int bc = g / TOPK;
    int b = bc / CT;
    int row = g_sidx[g];
    const float4* src = (const float4*)(db + ((size_t)b * NDB + row) * LEN);
    float4* dst = (float4*)(out + (size_t)g * LEN);
    int tid = threadIdx.x;
    dst[tid] = src[tid];
    dst[tid + 256] = src[tid + 256];
}

// ---------------- launch ----------------------------------------------------
extern "C" void kernel_launch(void* const* d_in, const int* in_sizes, int n_in,
                              void* d_out, int out_size) {
    const float* tgt = (const float*)d_in[0];
    const float* db  = (const float*)d_in[1];
    if (n_in >= 2 && in_sizes[0] > in_sizes[1]) {
        tgt = (const float*)d_in[1];
        db  = (const float*)d_in[0];
    }
    float* out = (float*)d_out;

    k_table<<<(NF * TABW + 255) / 256, 256>>>();
    k_xspec<<<BATCH * CT, 256>>>(tgt);
    k_scores<<<BATCH * NDB, 256>>>(db);
    k_sel<<<BATCH * CT, 256>>>();
    k_gather<<<BATCH * CT * TOPK, 256>>>(db, out);
}

// round 7
// speedup vs baseline: 2.2859x; 1.0377x over previous
#include <cuda_runtime.h>
#include <cuda_bf16.h>
#include <math.h>

#define BATCH 8
#define CT 16
#define LEN 2048
#define NDB 2048
#define NSEG 31
#define NPS 128
#define STEP 64
#define NF 65
#define TABW 66            // padded table stride (16B-aligned float2 rows)
#define TOPK 32
#define TN 4               // DB rows per k_scores block
#define EPSV 1e-12f
#define PI_D 3.14159265358979323846264338327950288

// ---------------- scratch (__device__ globals; no allocation allowed) ------
__device__ float2 g_tab[NF * TABW];                // [t*TABW+f], t=0..64: {w*cos, -w*sin}
__device__ float2 g_X[BATCH * CT * NSEG * NF];     // target spectra
__device__ float  g_Pxx[BATCH * CT * NF];
__device__ float  g_scores[BATCH * CT * NDB];
__device__ int    g_sidx[BATCH * CT * TOPK];

// ---------------- kernel 0: half twiddle table (Hann folded, double prec) --
__global__ void k_table() {
    int i = blockIdx.x * blockDim.x + threadIdx.x;
    if (i < NF * TABW) {
        int t = i / TABW, f = i % TABW;
        if (f < NF) {
            double w = 0.5 - 0.5 * cos(2.0 * PI_D * (double)t / (double)NPS);
            double ang = 2.0 * PI_D * (double)f * (double)t / (double)NPS;
            float ws = (t == 0 || t == 64) ? 0.f : (float)(-w * sin(ang));
            g_tab[i] = make_float2((float)(w * cos(ang)), ws);
        } else {
            g_tab[i] = make_float2(0.f, 0.f);
        }
    }
}

// ---------------- kernel 1: X spectra + Pxx (one block per (b,c)) ----------
__global__ __launch_bounds__(256) void k_xspec(const float* __restrict__ tgt) {
    int bc = blockIdx.x;
    int tid = threadIdx.x;
    __shared__ float sx[2176];
    __shared__ float smu[32];
    __shared__ float2 sY[NSEG * NF];

    const float* src = tgt + (size_t)bc * LEN;
    for (int i = tid; i < LEN; i += 256) sx[i] = src[i];
    for (int i = LEN + tid; i < 2176; i += 256) sx[i] = 0.f;
    __syncthreads();
    if (tid < 32) {
        float acc = 0.f;
        if (tid < NSEG) {
            const float* p = &sx[tid * STEP];
            for (int t = 0; t < NPS; t++) acc += p[t];
        }
        smu[tid] = acc * (1.f / NPS);
    }
    __syncthreads();
    for (int o = tid; o < NSEG * NF; o += 256) {
        int s = o / NF, f = o % NF;
        const float* fr = &sx[s * STEP];
        float mu = smu[s];
        float ar = 0.f, ai = 0.f;
        {
            float v0 = fr[0] - mu;
            float2 tb = g_tab[f];                 // t=0
            ar = fmaf(v0, tb.x, ar);
        }
        for (int t = 1; t < 64; t++) {
            float a = (fr[t] - mu) + (fr[128 - t] - mu);
            float d = fr[t] - fr[128 - t];
            float2 tb = g_tab[t * TABW + f];
            ar = fmaf(a, tb.x, ar);
            ai = fmaf(d, tb.y, ai);
        }
        {
            float v64 = fr[64] - mu;
            float2 tb = g_tab[64 * TABW + f];
            ar = fmaf(v64, tb.x, ar);
        }
        sY[o] = make_float2(ar, ai);
        g_X[(size_t)bc * (NSEG * NF) + o] = make_float2(ar, ai);
    }
    __syncthreads();
    if (tid < NF) {
        float acc = 0.f;
        for (int s = 0; s < NSEG; s++) {
            float2 y = sY[s * NF + tid];
            acc = fmaf(y.x, y.x, fmaf(y.y, y.y, acc));
        }
        g_Pxx[bc * NF + tid] = acc * (1.f / NSEG);
    }
}

// ---------------- kernel 2: scores (one block per 4 DB rows) ---------------
// Per row: lane=segment / warp=8-freq DFT (uniform LDG.128 + fma.rn.f32x2).
// Then ONE Pxy pass: each X value loaded once, dotted against 4 Y rows.
__global__ __launch_bounds__(256) void k_scores(const float* __restrict__ db) {
    int blk = blockIdx.x;                      // b * (NDB/TN) + ntile
    int b = blk / (NDB / TN);
    int n0 = (blk % (NDB / TN)) * TN;
    int tid = threadIdx.x;

    // pool: sx (2176) | sAD (32*129=4128) ; scoh (TN*1040=4160) overlays pool
    __shared__ float  pool[6304];
    __shared__ float  smu[32];
    __shared__ float2 sY[TN * NSEG * NF];      // 64480 B
    __shared__ float  spyy[TN * NF];
    float* sx  = pool;
    float* sAD = pool + 2176;
    float* scoh = pool;                        // alias, used after DFTs done

    for (int r = 0; r < TN; r++) {
        // ---- load row ----
        const float4* src = (const float4*)(db + ((size_t)b * NDB + n0 + r) * LEN);
        for (int i = tid; i < LEN / 4; i += 256) ((float4*)sx)[i] = src[i];
        for (int i = LEN + tid; i < 2176; i += 256) sx[i] = 0.f;
        __syncthreads();

        // ---- segment means (ascending t) ----
        if (tid < 32) {
            float acc = 0.f;
            if (tid < NSEG) {
                const float* p = &sx[tid * STEP];
                for (int t = 0; t < NPS; t++) acc += p[t];
            }
            smu[tid] = acc * (1.f / NPS);
        }
        __syncthreads();

        // ---- fold A/D (stride 129) ----
        for (int i = tid; i < NSEG * 64; i += 256) {
            int s = i >> 6, t = i & 63;
            float mu = smu[s];
            const float* fr = &sx[s * STEP];
            int base = s * 129;
            if (t == 0) {
                sAD[base]       = fr[0] - mu;
                sAD[base + 64]  = fr[64] - mu;
                sAD[base + 128] = 0.f;
            } else {
                float x1 = fr[t], x2 = fr[128 - t];
                sAD[base + t]      = (x1 - mu) + (x2 - mu);
                sAD[base + 64 + t] = x1 - x2;
            }
        }
        for (int i = 31 * 129 + tid; i < 32 * 129; i += 256) sAD[i] = 0.f;
        __syncthreads();

        // ---- DFT: warp w -> freqs [8w,8w+8) (+ f=64 on warp 0); lane=seg ----
        {
            int w = tid >> 5, lane = tid & 31;
            const float* p = &sAD[lane * 129];
            int f0 = w * 8;
            unsigned long long acc[8] = {0ull,0ull,0ull,0ull,0ull,0ull,0ull,0ull};
            unsigned long long acc64 = 0ull;
            #pragma unroll 5
            for (int t = 0; t <= 64; t++) {
                float A = p[t], D = p[64 + t];
                unsigned long long ad;
                asm("mov.b64 %0, {%1,%2};" : "=l"(ad)
                    : "r"(__float_as_uint(A)), "r"(__float_as_uint(D)));
                const ulonglong2* tq =
                    (const ulonglong2*)(g_tab + (size_t)t * TABW + f0);
                ulonglong2 q0 = __ldg(tq);
                ulonglong2 q1 = __ldg(tq + 1);
                ulonglong2 q2 = __ldg(tq + 2);
                ulonglong2 q3 = __ldg(tq + 3);
                asm("fma.rn.f32x2 %0, %1, %2, %0;" : "+l"(acc[0]) : "l"(ad), "l"(q0.x));
                asm("fma.rn.f32x2 %0, %1, %2, %0;" : "+l"(acc[1]) : "l"(ad), "l"(q0.y));
                asm("fma.rn.f32x2 %0, %1, %2, %0;" : "+l"(acc[2]) : "l"(ad), "l"(q1.x));
                asm("fma.rn.f32x2 %0, %1, %2, %0;" : "+l"(acc[3]) : "l"(ad), "l"(q1.y));
                asm("fma.rn.f32x2 %0, %1, %2, %0;" : "+l"(acc[4]) : "l"(ad), "l"(q2.x));
                asm("fma.rn.f32x2 %0, %1, %2, %0;" : "+l"(acc[5]) : "l"(ad), "l"(q2.y));
                asm("fma.rn.f32x2 %0, %1, %2, %0;" : "+l"(acc[6]) : "l"(ad), "l"(q3.x));
                asm("fma.rn.f32x2 %0, %1, %2, %0;" : "+l"(acc[7]) : "l"(ad), "l"(q3.y));
                if (w == 0) {
                    unsigned long long t64 =
                        *(const unsigned long long*)(g_tab + (size_t)t * TABW + 64);
                    asm("fma.rn.f32x2 %0, %1, %2, %0;" : "+l"(acc64) : "l"(ad), "l"(t64));
                }
            }
            if (lane < NSEG) {
                float2* dst = &sY[r * NSEG * NF + lane * NF];
                #pragma unroll
                for (int j = 0; j < 8; j++) {
                    unsigned int lo, hi;
                    asm("mov.b64 {%0,%1}, %2;" : "=r"(lo), "=r"(hi) : "l"(acc[j]));
                    dst[f0 + j] = make_float2(__uint_as_float(lo), __uint_as_float(hi));
                }
                if (w == 0) {
                    unsigned int lo, hi;
                    asm("mov.b64 {%0,%1}, %2;" : "=r"(lo), "=r"(hi) : "l"(acc64));
                    dst[64] = make_float2(__uint_as_float(lo), __uint_as_float(hi));
                }
            }
        }
        __syncthreads();
    }

    // ---- Pyy for all 4 rows ----
    for (int it = tid; it < TN * NF; it += 256) {
        int r = it / NF, f = it % NF;
        const float2* Yp = &sY[r * NSEG * NF + f];
        float acc = 0.f;
        #pragma unroll 4
        for (int s = 0; s < NSEG; s++) {
            float2 y = Yp[s * NF];
            acc = fmaf(y.x, y.x, fmaf(y.y, y.y, acc));
        }
        spyy[it] = acc * (1.f / NSEG);
    }
    __syncthreads();

    // ---- Pxy + coherence: X loaded once, dotted vs 4 rows ----
    for (int item = tid; item < CT * NF; item += 256) {
        int c = item / NF, f = item % NF;
        const float2* Xp = g_X + ((size_t)(b * CT + c)) * (NSEG * NF) + f;
        const float2* Y0 = &sY[0 * NSEG * NF + f];
        const float2* Y1 = &sY[1 * NSEG * NF + f];
        const float2* Y2 = &sY[2 * NSEG * NF + f];
        const float2* Y3 = &sY[3 * NSEG * NF + f];
        float pr0 = 0.f, pi0 = 0.f, pr1 = 0.f, pi1 = 0.f;
        float pr2 = 0.f, pi2 = 0.f, pr3 = 0.f, pi3 = 0.f;
        #pragma unroll 2
        for (int s = 0; s < NSEG; s++) {
            float2 xv = __ldg(&Xp[s * NF]);
            float2 y0 = Y0[s * NF];
            float2 y1 = Y1[s * NF];
            float2 y2 = Y2[s * NF];
            float2 y3 = Y3[s * NF];
            pr0 = fmaf(xv.x, y0.x, fmaf(xv.y, y0.y, pr0));
            pi0 = fmaf(xv.y, y0.x, fmaf(-xv.x, y0.y, pi0));
            pr1 = fmaf(xv.x, y1.x, fmaf(xv.y, y1.y, pr1));
            pi1 = fmaf(xv.y, y1.x, fmaf(-xv.x, y1.y, pi1));
            pr2 = fmaf(xv.x, y2.x, fmaf(xv.y, y2.y, pr2));
            pi2 = fmaf(xv.y, y2.x, fmaf(-xv.x, y2.y, pi2));
            pr3 = fmaf(xv.x, y3.x, fmaf(xv.y, y3.y, pr3));
            pi3 = fmaf(xv.y, y3.x, fmaf(-xv.x, y3.y, pi3));
        }
        float pxx = g_Pxx[(b * CT + c) * NF + f];
        pr0 *= (1.f / NSEG); pi0 *= (1.f / NSEG);
        pr1 *= (1.f / NSEG); pi1 *= (1.f / NSEG);
        pr2 *= (1.f / NSEG); pi2 *= (1.f / NSEG);
        pr3 *= (1.f / NSEG); pi3 *= (1.f / NSEG);
        scoh[0 * 1040 + item] = fmaf(pr0, pr0, pi0 * pi0) / fmaf(pxx, spyy[0 * NF + f], EPSV);
        scoh[1 * 1040 + item] = fmaf(pr1, pr1, pi1 * pi1) / fmaf(pxx, spyy[1 * NF + f], EPSV);
        scoh[2 * 1040 + item] = fmaf(pr2, pr2, pi2 * pi2) / fmaf(pxx, spyy[2 * NF + f], EPSV);
        scoh[3 * 1040 + item] = fmaf(pr3, pr3, pi3 * pi3) / fmaf(pxx, spyy[3 * NF + f], EPSV);
    }
    __syncthreads();

    // ---- scores: ascending-f sums ----
    if (tid < CT * TN) {
        int c = tid & (CT - 1), r = tid >> 4;
        const float* p = &scoh[r * 1040 + c * NF];
        float acc = 0.f;
        for (int f = 0; f < NF; f++) acc += p[f];
        g_scores[(size_t)(b * CT + c) * NDB + n0 + r] = acc * (1.f / NF);
    }
}

// ---------------- kernel 3a: top-32 selection (one block per (b,c)) --------
__global__ __launch_bounds__(256) void k_sel() {
    int bc = blockIdx.x;
    int tid = threadIdx.x;
    __shared__ float ss[NDB];
    __shared__ float rv[256];
    __shared__ int ri[256];

    for (int i = tid; i < NDB; i += 256) ss[i] = g_scores[(size_t)bc * NDB + i];
    __syncthreads();

    for (int k = 0; k < TOPK; k++) {
        float bv = -3.402823466e+38f;
        int bi = NDB;
        for (int i = tid; i < NDB; i += 256) {
            float v = ss[i];
            if (v > bv) { bv = v; bi = i; }
        }
        rv[tid] = bv; ri[tid] = bi;
        __syncthreads();
        for (int ofs = 128; ofs > 0; ofs >>= 1) {
            if (tid < ofs) {
                float ov = rv[tid + ofs]; int oi = ri[tid + ofs];
                if (ov > rv[tid] || (ov == rv[tid] && oi < ri[tid])) {
                    rv[tid] = ov; ri[tid] = oi;
                }
            }
            __syncthreads();
        }
        if (tid == 0) { g_sidx[bc * TOPK + k] = ri[0]; ss[ri[0]] = -3.402823466e+38f; }
        __syncthreads();
    }
}

// ---------------- kernel 3b: gather (one block per (b,c,k)) ----------------
__global__ __launch_bounds__(256) void k_gather(const float* __restrict__ db,
                                                float* __restrict__ out) {
    int g = blockIdx.x;
    int bc = g / TOPK;
    int b = bc / CT;
    int row = g_sidx[g];
    const float4* src = (const float4*)(db + ((size_t)b * NDB + row) * LEN);
    float4* dst = (float4*)(out + (size_t)g * LEN);
    int tid = threadIdx.x;
    dst[tid] = src[tid];
    dst[tid + 256] = src[tid + 256];
}

// ---------------- launch ----------------------------------------------------
extern "C" void kernel_launch(void* const* d_in, const int* in_sizes, int n_in,
                              void* d_out, int out_size) {
    const float* tgt = (const float*)d_in[0];
    const float* db  = (const float*)d_in[1];
    if (n_in >= 2 && in_sizes[0] > in_sizes[1]) {
        tgt = (const float*)d_in[1];
        db  = (const float*)d_in[0];
    }
    float* out = (float*)d_out;

    k_table<<<(NF * TABW + 255) / 256, 256>>>();
    k_xspec<<<BATCH * CT, 256>>>(tgt);
    k_scores<<<BATCH * (NDB / TN), 256>>>(db);
    k_sel<<<BATCH * CT, 256>>>();
    k_gather<<<BATCH * CT * TOPK, 256>>>(db, out);
}

// round 8
// speedup vs baseline: 2.5386x; 1.1105x over previous
#include <cuda_runtime.h>
#include <cuda_bf16.h>
#include <math.h>

#define BATCH 8
#define CT 16
#define LEN 2048
#define NDB 2048
#define NSEG 31
#define NPS 128
#define STEP 64
#define NF 65
#define TABW 66            // table row stride in float2 (16B-aligned rows)
#define TOPK 32
#define TN 2               // DB rows per k_scores block
#define EPSV 1e-12f
#define PI_D 3.14159265358979323846264338327950288

typedef unsigned long long ull;

// ---------------- scratch (__device__ globals; no allocation allowed) ------
__device__ float2 g_tab[NF * TABW];                // [t*TABW+f]: {w*cos, -w*sin}
__device__ float2 g_X[BATCH * CT * NSEG * NF];     // target spectra
__device__ float  g_Pxx[BATCH * CT * NF];
__device__ float  g_scores[BATCH * CT * NDB];
__device__ int    g_sidx[BATCH * CT * TOPK];

// ---------------- kernel 0: half twiddle table (Hann folded, double prec) --
__global__ void k_table() {
    int i = blockIdx.x * blockDim.x + threadIdx.x;
    if (i < NF * TABW) {
        int t = i / TABW, f = i % TABW;
        if (f < NF) {
            double w = 0.5 - 0.5 * cos(2.0 * PI_D * (double)t / (double)NPS);
            double ang = 2.0 * PI_D * (double)f * (double)t / (double)NPS;
            float ws = (t == 0 || t == 64) ? 0.f : (float)(-w * sin(ang));
            g_tab[i] = make_float2((float)(w * cos(ang)), ws);
        } else {
            g_tab[i] = make_float2(0.f, 0.f);
        }
    }
}

// ---------------- kernel 1: X spectra + Pxx (one block per (b,c)) ----------
__global__ __launch_bounds__(256) void k_xspec(const float* __restrict__ tgt) {
    int bc = blockIdx.x;
    int tid = threadIdx.x;
    __shared__ float sx[2176];
    __shared__ float smu[32];
    __shared__ float2 sY[NSEG * NF];

    const float* src = tgt + (size_t)bc * LEN;
    for (int i = tid; i < LEN; i += 256) sx[i] = src[i];
    for (int i = LEN + tid; i < 2176; i += 256) sx[i] = 0.f;
    __syncthreads();
    if (tid < 32) {
        float acc = 0.f;
        if (tid < NSEG) {
            const float* p = &sx[tid * STEP];
            for (int t = 0; t < NPS; t++) acc += p[t];
        }
        smu[tid] = acc * (1.f / NPS);
    }
    __syncthreads();
    for (int o = tid; o < NSEG * NF; o += 256) {
        int s = o / NF, f = o % NF;
        const float* fr = &sx[s * STEP];
        float mu = smu[s];
        float ar = 0.f, ai = 0.f;
        {
            float v0 = fr[0] - mu;
            float2 tb = g_tab[f];                 // t=0
            ar = fmaf(v0, tb.x, ar);
        }
        for (int t = 1; t < 64; t++) {
            float a = (fr[t] - mu) + (fr[128 - t] - mu);
            float d = fr[t] - fr[128 - t];
            float2 tb = g_tab[t * TABW + f];
            ar = fmaf(a, tb.x, ar);
            ai = fmaf(d, tb.y, ai);
        }
        {
            float v64 = fr[64] - mu;
            float2 tb = g_tab[64 * TABW + f];
            ar = fmaf(v64, tb.x, ar);
        }
        sY[o] = make_float2(ar, ai);
        g_X[(size_t)bc * (NSEG * NF) + o] = make_float2(ar, ai);
    }
    __syncthreads();
    if (tid < NF) {
        float acc = 0.f;
        for (int s = 0; s < NSEG; s++) {
            float2 y = sY[s * NF + tid];
            acc = fmaf(y.x, y.x, fmaf(y.y, y.y, acc));
        }
        g_Pxx[bc * NF + tid] = acc * (1.f / NSEG);
    }
}

// ---------------- kernel 2: scores (one block per TN=2 DB rows) ------------
// Twiddle table staged to SMEM once per block; A/D fold interleaved as float2
// so the f32x2 FMA operand is a single LDS.64. DFT reads are LDS-only.
__global__ __launch_bounds__(256) void k_scores(const float* __restrict__ db,
                                                int blk_base) {
    int blk = blk_base + blockIdx.x;           // b * (NDB/TN) + ntile
    int b = blk / (NDB / TN);
    int n0 = (blk % (NDB / TN)) * TN;
    int tid = threadIdx.x;

    __shared__ float2 sTab[NF * TABW];         // 34320 B, per-block copy
    __shared__ float  sx[2176];                // row buf; reused as scoh
    __shared__ float2 sAD2[32 * 67];           // (A,D) pairs, stride 67
    __shared__ float  smu[32];
    __shared__ float2 sY[TN * NSEG * NF];      // 32240 B
    __shared__ float  spyy[TN * NF];
    float* scoh = sx;

    // ---- stage table ----
    for (int i = tid; i < NF * TABW / 2; i += 256)
        ((float4*)sTab)[i] = ((const float4*)g_tab)[i];
    __syncthreads();

    for (int r = 0; r < TN; r++) {
        const float4* src = (const float4*)(db + ((size_t)b * NDB + n0 + r) * LEN);
        for (int i = tid; i < LEN / 4; i += 256) ((float4*)sx)[i] = src[i];
        for (int i = LEN + tid; i < 2176; i += 256) sx[i] = 0.f;
        __syncthreads();

        if (tid < 32) {
            float acc = 0.f;
            if (tid < NSEG) {
                const float* p = &sx[tid * STEP];
                for (int t = 0; t < NPS; t++) acc += p[t];
            }
            smu[tid] = acc * (1.f / NPS);
        }
        __syncthreads();

        // ---- fold: (A,D) interleaved, row stride 67 (conflict-free) ----
        for (int i = tid; i < 32 * 65; i += 256) {
            int s = i / 65, t = i % 65;
            if (s < NSEG) {
                float mu = smu[s];
                const float* fr = &sx[s * STEP];
                float A, D;
                if (t == 0)       { A = fr[0]  - mu; D = 0.f; }
                else if (t == 64) { A = fr[64] - mu; D = 0.f; }
                else {
                    float x1 = fr[t], x2 = fr[128 - t];
                    A = (x1 - mu) + (x2 - mu);
                    D = x1 - x2;
                }
                sAD2[s * 67 + t] = make_float2(A, D);
            } else {
                sAD2[s * 67 + t] = make_float2(0.f, 0.f);
            }
        }
        __syncthreads();

        // ---- DFT: warp w -> freqs [8w,8w+8) (+ f=64 on warp 0); lane=seg --
        {
            int w = tid >> 5, lane = tid & 31;
            const float2* adp = &sAD2[lane * 67];
            int f0 = w * 8;
            ull acc[8] = {0ull,0ull,0ull,0ull,0ull,0ull,0ull,0ull};
            ull acc64 = 0ull;
            #pragma unroll 5
            for (int t = 0; t <= 64; t++) {
                ull ad = *(const ull*)&adp[t];                   // LDS.64 (A,D)
                const ulonglong2* tq = (const ulonglong2*)&sTab[t * TABW + f0];
                ulonglong2 q0 = tq[0];
                ulonglong2 q1 = tq[1];
                ulonglong2 q2 = tq[2];
                ulonglong2 q3 = tq[3];
                asm("fma.rn.f32x2 %0, %1, %2, %0;" : "+l"(acc[0]) : "l"(ad), "l"(q0.x));
                asm("fma.rn.f32x2 %0, %1, %2, %0;" : "+l"(acc[1]) : "l"(ad), "l"(q0.y));
                asm("fma.rn.f32x2 %0, %1, %2, %0;" : "+l"(acc[2]) : "l"(ad), "l"(q1.x));
                asm("fma.rn.f32x2 %0, %1, %2, %0;" : "+l"(acc[3]) : "l"(ad), "l"(q1.y));
                asm("fma.rn.f32x2 %0, %1, %2, %0;" : "+l"(acc[4]) : "l"(ad), "l"(q2.x));
                asm("fma.rn.f32x2 %0, %1, %2, %0;" : "+l"(acc[5]) : "l"(ad), "l"(q2.y));
                asm("fma.rn.f32x2 %0, %1, %2, %0;" : "+l"(acc[6]) : "l"(ad), "l"(q3.x));
                asm("fma.rn.f32x2 %0, %1, %2, %0;" : "+l"(acc[7]) : "l"(ad), "l"(q3.y));
                if (w == 0) {
                    ull t64 = *(const ull*)&sTab[t * TABW + 64];
                    asm("fma.rn.f32x2 %0, %1, %2, %0;" : "+l"(acc64) : "l"(ad), "l"(t64));
                }
            }
            if (lane < NSEG) {
                float2* dst = &sY[r * NSEG * NF + lane * NF];
                #pragma unroll
                for (int j = 0; j < 8; j++) {
                    unsigned int lo, hi;
                    asm("mov.b64 {%0,%1}, %2;" : "=r"(lo), "=r"(hi) : "l"(acc[j]));
                    dst[f0 + j] = make_float2(__uint_as_float(lo), __uint_as_float(hi));
                }
                if (w == 0) {
                    unsigned int lo, hi;
                    asm("mov.b64 {%0,%1}, %2;" : "=r"(lo), "=r"(hi) : "l"(acc64));
                    dst[64] = make_float2(__uint_as_float(lo), __uint_as_float(hi));
                }
            }
        }
        __syncthreads();
    }

    // ---- Pyy for both rows ----
    for (int it = tid; it < TN * NF; it += 256) {
        int r = it / NF, f = it % NF;
        const float2* Yp = &sY[r * NSEG * NF + f];
        float acc = 0.f;
        #pragma unroll 4
        for (int s = 0; s < NSEG; s++) {
            float2 y = Yp[s * NF];
            acc = fmaf(y.x, y.x, fmaf(y.y, y.y, acc));
        }
        spyy[it] = acc * (1.f / NSEG);
    }
    __syncthreads();

    // ---- Pxy + coherence: X loaded once, dotted vs 2 rows ----
    for (int item = tid; item < CT * NF; item += 256) {
        int c = item / NF, f = item % NF;
        const float2* Xp = g_X + ((size_t)(b * CT + c)) * (NSEG * NF) + f;
        const float2* Y0 = &sY[0 * NSEG * NF + f];
        const float2* Y1 = &sY[1 * NSEG * NF + f];
        float pr0 = 0.f, pi0 = 0.f, pr1 = 0.f, pi1 = 0.f;
        #pragma unroll 4
        for (int s = 0; s < NSEG; s++) {
            float2 xv = __ldg(&Xp[s * NF]);
            float2 y0 = Y0[s * NF];
            float2 y1 = Y1[s * NF];
            pr0 = fmaf(xv.x, y0.x, fmaf(xv.y, y0.y, pr0));
            pi0 = fmaf(xv.y, y0.x, fmaf(-xv.x, y0.y, pi0));
            pr1 = fmaf(xv.x, y1.x, fmaf(xv.y, y1.y, pr1));
            pi1 = fmaf(xv.y, y1.x, fmaf(-xv.x, y1.y, pi1));
        }
        float pxx = g_Pxx[(b * CT + c) * NF + f];
        pr0 *= (1.f / NSEG); pi0 *= (1.f / NSEG);
        pr1 *= (1.f / NSEG); pi1 *= (1.f / NSEG);
        scoh[0 * 1040 + item] = fmaf(pr0, pr0, pi0 * pi0) / fmaf(pxx, spyy[0 * NF + f], EPSV);
        scoh[1 * 1040 + item] = fmaf(pr1, pr1, pi1 * pi1) / fmaf(pxx, spyy[1 * NF + f], EPSV);
    }
    __syncthreads();

    // ---- scores: ascending-f sums ----
    if (tid < CT * TN) {
        int c = tid & (CT - 1), r = tid >> 4;
        const float* p = &scoh[r * 1040 + c * NF];
        float acc = 0.f;
        for (int f = 0; f < NF; f++) acc += p[f];
        g_scores[(size_t)(b * CT + c) * NDB + n0 + r] = acc * (1.f / NF);
    }
}

// ---------------- kernel 3a: top-32 selection (one block per (b,c)) --------
__global__ __launch_bounds__(256) void k_sel() {
    int bc = blockIdx.x;
    int tid = threadIdx.x;
    __shared__ float ss[NDB];
    __shared__ float rv[256];
    __shared__ int ri[256];

    for (int i = tid; i < NDB; i += 256) ss[i] = g_scores[(size_t)bc * NDB + i];
    __syncthreads();

    for (int k = 0; k < TOPK; k++) {
        float bv = -3.402823466e+38f;
        int bi = NDB;
        for (int i = tid; i < NDB; i += 256) {
            float v = ss[i];
            if (v > bv) { bv = v; bi = i; }
        }
        rv[tid] = bv; ri[tid] = bi;
        __syncthreads();
        for (int ofs = 128; ofs > 0; ofs >>= 1) {
            if (tid < ofs) {
                float ov = rv[tid + ofs]; int oi = ri[tid + ofs];
                if (ov > rv[tid] || (ov == rv[tid] && oi < ri[tid])) {
                    rv[tid] = ov; ri[tid] = oi;
                }
            }
            __syncthreads();
        }
        if (tid == 0) { g_sidx[bc * TOPK + k] = ri[0]; ss[ri[0]] = -3.402823466e+38f; }
        __syncthreads();
    }
}

// ---------------- kernel 3b: gather (one block per (b,c,k)) ----------------
__global__ __launch_bounds__(256) void k_gather(const float* __restrict__ db,
                                                float* __restrict__ out) {
    int g = blockIdx.x;
    int bc = g / TOPK;
    int b = bc / CT;
    int row = g_sidx[g];
    const float4* src = (const float4*)(db + ((size_t)b * NDB + row) * LEN);
    float4* dst = (float4*)(out + (size_t)g * LEN);
    int tid = threadIdx.x;
    dst[tid] = src[tid];
    dst[tid + 256] = src[tid + 256];
}

// ---------------- launch ----------------------------------------------------
extern "C" void kernel_launch(void* const* d_in, const int* in_sizes, int n_in,
                              void* d_out, int out_size) {
    const float* tgt = (const float*)d_in[0];
    const float* db  = (const float*)d_in[1];
    if (n_in >= 2 && in_sizes[0] > in_sizes[1]) {
        tgt = (const float*)d_in[1];
        db  = (const float*)d_in[0];
    }
    float* out = (float*)d_out;

    int half = BATCH * (NDB / TN) / 2;         // 512 blocks per half
    k_table<<<(NF * TABW + 255) / 256, 256>>>();
    k_xspec<<<BATCH * CT, 256>>>(tgt);
    k_scores<<<half, 256>>>(db, 0);            // launch slot 3
    k_scores<<<half, 256>>>(db, half);         // launch slot 4 (profiler target)
    k_sel<<<BATCH * CT, 256>>>();
    k_gather<<<BATCH * CT * TOPK, 256>>>(db, out);
}

// round 9
// speedup vs baseline: 2.9119x; 1.1470x over previous
#include <cuda_runtime.h>
#include <cuda_bf16.h>
#include <math.h>

#define BATCH 8
#define CT 16
#define LEN 2048
#define NDB 2048
#define NSEG 31
#define NPS 128
#define STEP 64
#define NF 65
#define TABW 66            // table row stride in float2 (16B-aligned rows)
#define TOPK 32
#define TN 2               // DB rows per k_scores block (fused in one t-loop)
#define EPSV 1e-12f
#define PI_D 3.14159265358979323846264338327950288

typedef unsigned long long ull;

// ---------------- scratch (__device__ globals; no allocation allowed) ------
__device__ float2 g_tab[NF * TABW];                // [t*TABW+f]: {w*cos, -w*sin}
__device__ float2 g_X[BATCH * CT * NSEG * NF];     // target spectra
__device__ float  g_Pxx[BATCH * CT * NF];
__device__ float  g_scores[BATCH * CT * NDB];
__device__ int    g_sidx[BATCH * CT * TOPK];

// ---------------- kernel 0: half twiddle table (Hann folded, double prec) --
__global__ void k_table() {
    int i = blockIdx.x * blockDim.x + threadIdx.x;
    if (i < NF * TABW) {
        int t = i / TABW, f = i % TABW;
        if (f < NF) {
            double w = 0.5 - 0.5 * cos(2.0 * PI_D * (double)t / (double)NPS);
            double ang = 2.0 * PI_D * (double)f * (double)t / (double)NPS;
            float ws = (t == 0 || t == 64) ? 0.f : (float)(-w * sin(ang));
            g_tab[i] = make_float2((float)(w * cos(ang)), ws);
        } else {
            g_tab[i] = make_float2(0.f, 0.f);
        }
    }
}

// ---------------- kernel 1: X spectra + Pxx (one block per (b,c)) ----------
__global__ __launch_bounds__(256) void k_xspec(const float* __restrict__ tgt) {
    int bc = blockIdx.x;
    int tid = threadIdx.x;
    __shared__ float sx[2176];
    __shared__ float smu[32];
    __shared__ float2 sY[NSEG * NF];

    const float* src = tgt + (size_t)bc * LEN;
    for (int i = tid; i < LEN; i += 256) sx[i] = src[i];
    for (int i = LEN + tid; i < 2176; i += 256) sx[i] = 0.f;
    __syncthreads();
    if (tid < 32) {
        float acc = 0.f;
        if (tid < NSEG) {
            const float* p = &sx[tid * STEP];
            for (int t = 0; t < NPS; t++) acc += p[t];
        }
        smu[tid] = acc * (1.f / NPS);
    }
    __syncthreads();
    for (int o = tid; o < NSEG * NF; o += 256) {
        int s = o / NF, f = o % NF;
        const float* fr = &sx[s * STEP];
        float mu = smu[s];
        float ar = 0.f, ai = 0.f;
        {
            float v0 = fr[0] - mu;
            float2 tb = g_tab[f];                 // t=0
            ar = fmaf(v0, tb.x, ar);
        }
        for (int t = 1; t < 64; t++) {
            float a = (fr[t] - mu) + (fr[128 - t] - mu);
            float d = fr[t] - fr[128 - t];
            float2 tb = g_tab[t * TABW + f];
            ar = fmaf(a, tb.x, ar);
            ai = fmaf(d, tb.y, ai);
        }
        {
            float v64 = fr[64] - mu;
            float2 tb = g_tab[64 * TABW + f];
            ar = fmaf(v64, tb.x, ar);
        }
        sY[o] = make_float2(ar, ai);
        g_X[(size_t)bc * (NSEG * NF) + o] = make_float2(ar, ai);
    }
    __syncthreads();
    if (tid < NF) {
        float acc = 0.f;
        for (int s = 0; s < NSEG; s++) {
            float2 y = sY[s * NF + tid];
            acc = fmaf(y.x, y.x, fmaf(y.y, y.y, acc));
        }
        g_Pxx[bc * NF + tid] = acc * (1.f / NSEG);
    }
}

// ---------------- helper: fold one row into (A,D) pairs --------------------
__device__ __forceinline__ void fold_row(const float* __restrict__ sx,
                                         const float* __restrict__ smu,
                                         float2* __restrict__ sAD, int tid) {
    for (int i = tid; i < 32 * 65; i += 256) {
        int s = i / 65, t = i % 65;
        if (s < NSEG) {
            float mu = smu[s];
            const float* fr = &sx[s * STEP];
            float A, D;
            if (t == 0)       { A = fr[0]  - mu; D = 0.f; }
            else if (t == 64) { A = fr[64] - mu; D = 0.f; }
            else {
                float x1 = fr[t], x2 = fr[128 - t];
                A = (x1 - mu) + (x2 - mu);
                D = x1 - x2;
            }
            sAD[s * 67 + t] = make_float2(A, D);
        } else {
            sAD[s * 67 + t] = make_float2(0.f, 0.f);
        }
    }
}

// ---------------- kernel 2: scores (one block per TN=2 DB rows) ------------
// Fused-row DFT: both rows share each table LDS.128 (6 LDS : 16 FFMA2 per
// warp-t). Phase-2 buffers (sY/scoh/spyy) overlay the dead sx+sAD pool.
__global__ __launch_bounds__(256, 2) void k_scores(const float* __restrict__ db,
                                                   int blk_base) {
    int blk = blk_base + blockIdx.x;           // b * (NDB/TN) + ntile
    int b = blk / (NDB / TN);
    int n0 = (blk % (NDB / TN)) * TN;
    int tid = threadIdx.x;

    __shared__ float2 sTab[NF * TABW];         // 34320 B, persists all phases
    __shared__ __align__(16) char pool[43520]; // phase1: sx|sADa|sADb, phase2: sY|scoh|spyy
    __shared__ float smu[32];

    float*  sx   = (float*)pool;                         // 8704 B
    float2* sADa = (float2*)(pool + 8704);               // 17152 B
    float2* sADb = (float2*)(pool + 25856);              // 17152 B
    float2* sY   = (float2*)pool;                        // 32240 B (phase 2)
    float*  scoh = (float*)(pool + 32240);               // 8320 B
    float*  spyy = (float*)(pool + 40560);               // 520 B

    // ---- stage table ----
    for (int i = tid; i < NF * TABW / 2; i += 256)
        ((float4*)sTab)[i] = ((const float4*)g_tab)[i];

    // ---- load + fold both rows ----
    for (int r = 0; r < TN; r++) {
        const float4* src = (const float4*)(db + ((size_t)b * NDB + n0 + r) * LEN);
        for (int i = tid; i < LEN / 4; i += 256) ((float4*)sx)[i] = src[i];
        __syncthreads();
        if (tid < 32) {
            float acc = 0.f;
            if (tid < NSEG) {
                const float* p = &sx[tid * STEP];
                for (int t = 0; t < NPS; t++) acc += p[t];
            }
            smu[tid] = acc * (1.f / NPS);
        }
        __syncthreads();
        fold_row(sx, smu, r == 0 ? sADa : sADb, tid);
        __syncthreads();
    }

    // ---- fused DFT: warp w -> freqs [8w,8w+8) (+f=64 on w0); lane=segment --
    {
        int w = tid >> 5, lane = tid & 31;
        const float2* adpA = &sADa[lane * 67];
        const float2* adpB = &sADb[lane * 67];
        int f0 = w * 8;
        ull accA[8] = {0,0,0,0,0,0,0,0};
        ull accB[8] = {0,0,0,0,0,0,0,0};
        ull accA64 = 0, accB64 = 0;
        #pragma unroll 5
        for (int t = 0; t <= 64; t++) {
            ull adA = *(const ull*)&adpA[t];               // LDS.64 (A,D) row0
            ull adB = *(const ull*)&adpB[t];               // LDS.64 (A,D) row1
            const ulonglong2* tq = (const ulonglong2*)&sTab[t * TABW + f0];
            ulonglong2 q0 = tq[0];
            ulonglong2 q1 = tq[1];
            ulonglong2 q2 = tq[2];
            ulonglong2 q3 = tq[3];
            asm("fma.rn.f32x2 %0, %1, %2, %0;" : "+l"(accA[0]) : "l"(adA), "l"(q0.x));
            asm("fma.rn.f32x2 %0, %1, %2, %0;" : "+l"(accB[0]) : "l"(adB), "l"(q0.x));
            asm("fma.rn.f32x2 %0, %1, %2, %0;" : "+l"(accA[1]) : "l"(adA), "l"(q0.y));
            asm("fma.rn.f32x2 %0, %1, %2, %0;" : "+l"(accB[1]) : "l"(adB), "l"(q0.y));
            asm("fma.rn.f32x2 %0, %1, %2, %0;" : "+l"(accA[2]) : "l"(adA), "l"(q1.x));
            asm("fma.rn.f32x2 %0, %1, %2, %0;" : "+l"(accB[2]) : "l"(adB), "l"(q1.x));
            asm("fma.rn.f32x2 %0, %1, %2, %0;" : "+l"(accA[3]) : "l"(adA), "l"(q1.y));
            asm("fma.rn.f32x2 %0, %1, %2, %0;" : "+l"(accB[3]) : "l"(adB), "l"(q1.y));
            asm("fma.rn.f32x2 %0, %1, %2, %0;" : "+l"(accA[4]) : "l"(adA), "l"(q2.x));
            asm("fma.rn.f32x2 %0, %1, %2, %0;" : "+l"(accB[4]) : "l"(adB), "l"(q2.x));
            asm("fma.rn.f32x2 %0, %1, %2, %0;" : "+l"(accA[5]) : "l"(adA), "l"(q2.y));
            asm("fma.rn.f32x2 %0, %1, %2, %0;" : "+l"(accB[5]) : "l"(adB), "l"(q2.y));
            asm("fma.rn.f32x2 %0, %1, %2, %0;" : "+l"(accA[6]) : "l"(adA), "l"(q3.x));
            asm("fma.rn.f32x2 %0, %1, %2, %0;" : "+l"(accB[6]) : "l"(adB), "l"(q3.x));
            asm("fma.rn.f32x2 %0, %1, %2, %0;" : "+l"(accA[7]) : "l"(adA), "l"(q3.y));
            asm("fma.rn.f32x2 %0, %1, %2, %0;" : "+l"(accB[7]) : "l"(adB), "l"(q3.y));
            if (w == 0) {
                ull t64 = *(const ull*)&sTab[t * TABW + 64];
                asm("fma.rn.f32x2 %0, %1, %2, %0;" : "+l"(accA64) : "l"(adA), "l"(t64));
                asm("fma.rn.f32x2 %0, %1, %2, %0;" : "+l"(accB64) : "l"(adB), "l"(t64));
            }
        }
        __syncthreads();                       // sAD dead for ALL warps before sY overlay
        if (lane < NSEG) {
            float2* dA = &sY[0 * NSEG * NF + lane * NF];
            float2* dB = &sY[1 * NSEG * NF + lane * NF];
            #pragma unroll
            for (int j = 0; j < 8; j++) {
                unsigned int lo, hi;
                asm("mov.b64 {%0,%1}, %2;" : "=r"(lo), "=r"(hi) : "l"(accA[j]));
                dA[f0 + j] = make_float2(__uint_as_float(lo), __uint_as_float(hi));
                asm("mov.b64 {%0,%1}, %2;" : "=r"(lo), "=r"(hi) : "l"(accB[j]));
                dB[f0 + j] = make_float2(__uint_as_float(lo), __uint_as_float(hi));
            }
            if (w == 0) {
                unsigned int lo, hi;
                asm("mov.b64 {%0,%1}, %2;" : "=r"(lo), "=r"(hi) : "l"(accA64));
                dA[64] = make_float2(__uint_as_float(lo), __uint_as_float(hi));
                asm("mov.b64 {%0,%1}, %2;" : "=r"(lo), "=r"(hi) : "l"(accB64));
                dB[64] = make_float2(__uint_as_float(lo), __uint_as_float(hi));
            }
        }
    }
    __syncthreads();

    // ---- Pyy for both rows ----
    for (int it = tid; it < TN * NF; it += 256) {
        int r = it / NF, f = it % NF;
        const float2* Yp = &sY[r * NSEG * NF + f];
        float acc = 0.f;
        #pragma unroll 4
        for (int s = 0; s < NSEG; s++) {
            float2 y = Yp[s * NF];
            acc = fmaf(y.x, y.x, fmaf(y.y, y.y, acc));
        }
        spyy[it] = acc * (1.f / NSEG);
    }
    __syncthreads();

    // ---- Pxy + coherence: X loaded once, dotted vs 2 rows ----
    for (int item = tid; item < CT * NF; item += 256) {
        int c = item / NF, f = item % NF;
        const float2* Xp = g_X + ((size_t)(b * CT + c)) * (NSEG * NF) + f;
        const float2* Y0 = &sY[0 * NSEG * NF + f];
        const float2* Y1 = &sY[1 * NSEG * NF + f];
        float pr0 = 0.f, pi0 = 0.f, pr1 = 0.f, pi1 = 0.f;
        #pragma unroll 4
        for (int s = 0; s < NSEG; s++) {
            float2 xv = __ldg(&Xp[s * NF]);
            float2 y0 = Y0[s * NF];
            float2 y1 = Y1[s * NF];
            pr0 = fmaf(xv.x, y0.x, fmaf(xv.y, y0.y, pr0));
            pi0 = fmaf(xv.y, y0.x, fmaf(-xv.x, y0.y, pi0));
            pr1 = fmaf(xv.x, y1.x, fmaf(xv.y, y1.y, pr1));
            pi1 = fmaf(xv.y, y1.x, fmaf(-xv.x, y1.y, pi1));
        }
        float pxx = g_Pxx[(b * CT + c) * NF + f];
        pr0 *= (1.f / NSEG); pi0 *= (1.f / NSEG);
        pr1 *= (1.f / NSEG); pi1 *= (1.f / NSEG);
        scoh[0 * 1040 + item] = fmaf(pr0, pr0, pi0 * pi0) / fmaf(pxx, spyy[0 * NF + f], EPSV);
        scoh[1 * 1040 + item] = fmaf(pr1, pr1, pi1 * pi1) / fmaf(pxx, spyy[1 * NF + f], EPSV);
    }
    __syncthreads();

    // ---- scores: ascending-f sums ----
    if (tid < CT * TN) {
        int c = tid & (CT - 1), r = tid >> 4;
        const float* p = &scoh[r * 1040 + c * NF];
        float acc = 0.f;
        for (int f = 0; f < NF; f++) acc += p[f];
        g_scores[(size_t)(b * CT + c) * NDB + n0 + r] = acc * (1.f / NF);
    }
}

// ---------------- kernel 3a: top-32 selection (one block per (b,c)) --------
__global__ __launch_bounds__(256) void k_sel() {
    int bc = blockIdx.x;
    int tid = threadIdx.x;
    __shared__ float ss[NDB];
    __shared__ float rv[256];
    __shared__ int ri[256];

    for (int i = tid; i < NDB; i += 256) ss[i] = g_scores[(size_t)bc * NDB + i];
    __syncthreads();

    for (int k = 0; k < TOPK; k++) {
        float bv = -3.402823466e+38f;
        int bi = NDB;
        for (int i = tid; i < NDB; i += 256) {
            float v = ss[i];
            if (v > bv) { bv = v; bi = i; }
        }
        rv[tid] = bv; ri[tid] = bi;
        __syncthreads();
        for (int ofs = 128; ofs > 0; ofs >>= 1) {
            if (tid < ofs) {
                float ov = rv[tid + ofs]; int oi = ri[tid + ofs];
                if (ov > rv[tid] || (ov == rv[tid] && oi < ri[tid])) {
                    rv[tid] = ov; ri[tid] = oi;
                }
            }
            __syncthreads();
        }
        if (tid == 0) { g_sidx[bc * TOPK + k] = ri[0]; ss[ri[0]] = -3.402823466e+38f; }
        __syncthreads();
    }
}

// ---------------- kernel 3b: gather (one block per (b,c,k)) ----------------
__global__ __launch_bounds__(256) void k_gather(const float* __restrict__ db,
                                                float* __restrict__ out) {
    int g = blockIdx.x;
    int bc = g / TOPK;
    int b = bc / CT;
    int row = g_sidx[g];
    const float4* src = (const float4*)(db + ((size_t)b * NDB + row) * LEN);
    float4* dst = (float4*)(out + (size_t)g * LEN);
    int tid = threadIdx.x;
    dst[tid] = src[tid];
    dst[tid + 256] = src[tid + 256];
}

// ---------------- launch ----------------------------------------------------
extern "C" void kernel_launch(void* const* d_in, const int* in_sizes, int n_in,
                              void* d_out, int out_size) {
    const float* tgt = (const float*)d_in[0];
    const float* db  = (const float*)d_in[1];
    if (n_in >= 2 && in_sizes[0] > in_sizes[1]) {
        tgt = (const float*)d_in[1];
        db  = (const float*)d_in[0];
    }
    float* out = (float*)d_out;

    int half = BATCH * (NDB / TN) / 2;         // 512 blocks per half
    k_table<<<(NF * TABW + 255) / 256, 256>>>();
    k_xspec<<<BATCH * CT, 256>>>(tgt);
    k_scores<<<half, 256>>>(db, 0);
    k_scores<<<half, 256>>>(db, half);         // profiler slot
    k_sel<<<BATCH * CT, 256>>>();
    k_gather<<<BATCH * CT * TOPK, 256>>>(db, out);
}